// round 1
// baseline (speedup 1.0000x reference)
#include <cuda_runtime.h>

// ---------------------------------------------------------------------------
// GaussianPolicy: spiking policy network forward pass.
//   B=2048, NIN=512, HID=1024, NACT=32, 5 frames repeated 3x -> 15 steps.
// Pipeline:
//   1) I[b,f,j,h] = state[b,f,:] @ wj^T + bj  (j=0..2)   3 GEMMs [10240,512]x[512,1024]
//   2) LIF scan over 15 steps -> x[b, h*4+k] = mean spikes   (elementwise)
//   3) two MLP heads: relu(x@w11^T+b11) -> relu(@w12^T+b12) -> @wm^T+bm = mean
//                     relu(x@w21^T+b21) -> relu(@w22^T+b22) -> clip(@ws^T+bs) = log_std
// Output: [mean | log_std] concatenated, fp32, 2*2048*32 elements.
// ---------------------------------------------------------------------------

namespace {
constexpr int BATCH  = 2048;
constexpr int NIN    = 512;
constexpr int HID    = 1024;
constexpr int NACT   = 32;
constexpr int FRAMES = 5;
}

// Scratch (alloc-free rule: __device__ globals)
__device__ float g_I [(size_t)BATCH * FRAMES * 3 * HID];  // [b, f, j, h]
__device__ float g_X [(size_t)BATCH * 4 * HID];           // [b, h*4+k]
__device__ float g_H1[(size_t)BATCH * HID];
__device__ float g_H2[(size_t)BATCH * HID];

// ---------------------------------------------------------------------------
// Generic NT SGEMM: C[M,N] = A[M,K] * W[N,K]^T + bias, optional ReLU.
// Requires M%128==0, N%128==0, K%8==0 (true for all uses here).
// 128x128 block, 8x8 per thread, 256 threads.
// ---------------------------------------------------------------------------
template<int EPI> // 0 = bias only, 1 = bias + relu
__global__ void __launch_bounds__(256) sgemm_nt_kernel(
    int M, int N, int K,
    const float* __restrict__ A, int lda,
    const float* __restrict__ W, int ldb,
    const float* __restrict__ bias,
    float* __restrict__ C, int ldc)
{
    constexpr int BM = 128, BN = 128, BK = 8, TM = 8, TN = 8;
    __shared__ float As[BK][BM];
    __shared__ float Bs[BK][BN];

    const int tid = threadIdx.x;
    const int bm  = blockIdx.y * BM;
    const int bn  = blockIdx.x * BN;
    const int tx  = tid & 15;       // 16 thread cols
    const int ty  = tid >> 4;       // 16 thread rows

    // global->shared load mapping: 128 rows x 8 cols = 256 float4
    const int lrow = tid >> 1;            // 0..127
    const int lcol = (tid & 1) * 4;       // 0 or 4

    const float* Ablk = A + (size_t)bm * lda;
    const float* Bblk = W + (size_t)bn * ldb;

    float acc[TM][TN];
    #pragma unroll
    for (int i = 0; i < TM; i++)
        #pragma unroll
        for (int j = 0; j < TN; j++) acc[i][j] = 0.f;

    for (int k0 = 0; k0 < K; k0 += BK) {
        float4 av = *(const float4*)(Ablk + (size_t)lrow * lda + k0 + lcol);
        float4 bv = *(const float4*)(Bblk + (size_t)lrow * ldb + k0 + lcol);
        As[lcol + 0][lrow] = av.x; As[lcol + 1][lrow] = av.y;
        As[lcol + 2][lrow] = av.z; As[lcol + 3][lrow] = av.w;
        Bs[lcol + 0][lrow] = bv.x; Bs[lcol + 1][lrow] = bv.y;
        Bs[lcol + 2][lrow] = bv.z; Bs[lcol + 3][lrow] = bv.w;
        __syncthreads();

        #pragma unroll
        for (int k = 0; k < BK; k++) {
            float ar[TM], br[TN];
            float4 t;
            t = *(const float4*)&As[k][ty * TM];     ar[0]=t.x; ar[1]=t.y; ar[2]=t.z; ar[3]=t.w;
            t = *(const float4*)&As[k][ty * TM + 4]; ar[4]=t.x; ar[5]=t.y; ar[6]=t.z; ar[7]=t.w;
            t = *(const float4*)&Bs[k][tx * TN];     br[0]=t.x; br[1]=t.y; br[2]=t.z; br[3]=t.w;
            t = *(const float4*)&Bs[k][tx * TN + 4]; br[4]=t.x; br[5]=t.y; br[6]=t.z; br[7]=t.w;
            #pragma unroll
            for (int i = 0; i < TM; i++)
                #pragma unroll
                for (int j = 0; j < TN; j++)
                    acc[i][j] = fmaf(ar[i], br[j], acc[i][j]);
        }
        __syncthreads();
    }

    #pragma unroll
    for (int i = 0; i < TM; i++) {
        const int row = bm + ty * TM + i;
        #pragma unroll
        for (int j = 0; j < TN; j++) {
            const int col = bn + tx * TN + j;
            float v = acc[i][j] + bias[col];
            if (EPI == 1) v = fmaxf(v, 0.f);
            C[(size_t)row * ldc + col] = v;
        }
    }
}

// ---------------------------------------------------------------------------
// LIF scan: per (b,h) lane, 5 frames x 3 repeats. Exact reference semantics:
//   inner uses OLD mem; mem1 = mem*0.2*(1-spike_old) + input; spike = mem1>0.8
// Accumulated spike counts are exact integers -> x = count/15 is exact.
// ---------------------------------------------------------------------------
__global__ void __launch_bounds__(256) scan_kernel(
    const float* __restrict__ I,   // [b, f, j, h]
    const float* __restrict__ wl,  // [3]
    const float* __restrict__ bl,  // [1]
    float* __restrict__ X)         // [b, h*4+k]
{
    const int idx = blockIdx.x * 256 + threadIdx.x;   // b*HID + h
    const int b = idx >> 10;
    const int h = idx & (HID - 1);
    if (b >= BATCH) return;

    const float wl0 = wl[0], wl1 = wl[1], wl2 = wl[2], blv = bl[0];
    float m0 = 0.f, m1 = 0.f, m2 = 0.f, m3 = 0.f;
    float s0 = 0.f, s1 = 0.f, s2 = 0.f, s3 = 0.f;
    float a0 = 0.f, a1 = 0.f, a2 = 0.f, a3 = 0.f;

    const float* Ib = I + (size_t)b * FRAMES * 3 * HID + h;
    #pragma unroll
    for (int f = 0; f < FRAMES; f++) {
        const float i1 = Ib[(f * 3 + 0) * HID];
        const float i2 = Ib[(f * 3 + 1) * HID];
        const float i3 = Ib[(f * 3 + 2) * HID];
        #pragma unroll
        for (int r = 0; r < 3; r++) {
            const float inner = fmaf(m0, wl0, fmaf(m1, wl1, fmaf(m2, wl2, blv)));
            m0 = (m0 * 0.2f) * (1.f - s0) + i1;
            m1 = (m1 * 0.2f) * (1.f - s1) + i2;
            m2 = (m2 * 0.2f) * (1.f - s2) + i3;
            m3 = (m3 * 0.2f) * (1.f - s3) + inner;
            s0 = (m0 > 0.8f) ? 1.f : 0.f;
            s1 = (m1 > 0.8f) ? 1.f : 0.f;
            s2 = (m2 > 0.8f) ? 1.f : 0.f;
            s3 = (m3 > 0.8f) ? 1.f : 0.f;
            a0 += s0; a1 += s1; a2 += s2; a3 += s3;
        }
    }
    const float inv = 1.f / 15.f;
    float4 v = make_float4(a0 * inv, a1 * inv, a2 * inv, a3 * inv);
    *(float4*)(X + (size_t)idx * 4) = v;
}

// ---------------------------------------------------------------------------
// Final tiny layer: out[b, o] = X[b,:HID] . W[o,:HID] + bias[o], optional clip.
// One block per batch row; 8 warps; warp-per-output, 4 passes over 32 outputs.
// ---------------------------------------------------------------------------
__global__ void __launch_bounds__(256) head_out_kernel(
    const float* __restrict__ X, const float* __restrict__ W,
    const float* __restrict__ bias, float* __restrict__ out, int doclip)
{
    __shared__ float xs[HID];
    const int b = blockIdx.x;
    const float* xrow = X + (size_t)b * HID;
    for (int i = threadIdx.x; i < HID; i += 256) xs[i] = xrow[i];
    __syncthreads();

    const int warp = threadIdx.x >> 5;
    const int lane = threadIdx.x & 31;
    for (int o = warp; o < NACT; o += 8) {
        const float* wrow = W + (size_t)o * HID;
        float acc = 0.f;
        #pragma unroll 4
        for (int k = lane; k < HID; k += 32)
            acc = fmaf(xs[k], wrow[k], acc);
        #pragma unroll
        for (int s = 16; s > 0; s >>= 1)
            acc += __shfl_xor_sync(0xffffffff, acc, s);
        if (lane == 0) {
            float v = acc + bias[o];
            if (doclip) v = fminf(fmaxf(v, -20.f), 2.f);
            out[(size_t)b * NACT + o] = v;
        }
    }
}

// ---------------------------------------------------------------------------
extern "C" void kernel_launch(void* const* d_in, const int* in_sizes, int n_in,
                              void* d_out, int out_size)
{
    const float* state = (const float*)d_in[0];
    const float* w1  = (const float*)d_in[1];  const float* b1  = (const float*)d_in[2];
    const float* w2  = (const float*)d_in[3];  const float* b2  = (const float*)d_in[4];
    const float* w3  = (const float*)d_in[5];  const float* b3  = (const float*)d_in[6];
    const float* wl  = (const float*)d_in[7];  const float* bl  = (const float*)d_in[8];
    const float* w11 = (const float*)d_in[9];  const float* b11 = (const float*)d_in[10];
    const float* w12 = (const float*)d_in[11]; const float* b12 = (const float*)d_in[12];
    const float* w21 = (const float*)d_in[13]; const float* b21 = (const float*)d_in[14];
    const float* w22 = (const float*)d_in[15]; const float* b22 = (const float*)d_in[16];
    const float* wm  = (const float*)d_in[17]; const float* bm  = (const float*)d_in[18];
    const float* ws  = (const float*)d_in[19]; const float* bs  = (const float*)d_in[20];
    float* out = (float*)d_out;

    float *pI, *pX, *pH1, *pH2;
    cudaGetSymbolAddress((void**)&pI,  g_I);
    cudaGetSymbolAddress((void**)&pX,  g_X);
    cudaGetSymbolAddress((void**)&pH1, g_H1);
    cudaGetSymbolAddress((void**)&pH2, g_H2);

    const dim3 blk(256);

    // Phase 1: 3 input GEMMs over the 5 unique frames (repeat-3x exploited).
    // I laid out [b, f, j, h] via ldc = 3*HID, column offsets j*HID.
    const dim3 g1(HID / 128, (BATCH * FRAMES) / 128);
    sgemm_nt_kernel<0><<<g1, blk>>>(BATCH * FRAMES, HID, NIN, state, NIN, w1, NIN, b1, pI + 0 * HID, 3 * HID);
    sgemm_nt_kernel<0><<<g1, blk>>>(BATCH * FRAMES, HID, NIN, state, NIN, w2, NIN, b2, pI + 1 * HID, 3 * HID);
    sgemm_nt_kernel<0><<<g1, blk>>>(BATCH * FRAMES, HID, NIN, state, NIN, w3, NIN, b3, pI + 2 * HID, 3 * HID);

    // Phase 2: LIF scan -> x [B, 4*HID]
    scan_kernel<<<(BATCH * HID) / 256, blk>>>(pI, wl, bl, pX);

    // Phase 3: MLP heads
    const dim3 g2(HID / 128, BATCH / 128);
    // mean path
    sgemm_nt_kernel<1><<<g2, blk>>>(BATCH, HID, 4 * HID, pX,  4 * HID, w11, 4 * HID, b11, pH1, HID);
    sgemm_nt_kernel<1><<<g2, blk>>>(BATCH, HID, HID,     pH1, HID,     w12, HID,     b12, pH2, HID);
    head_out_kernel<<<BATCH, blk>>>(pH2, wm, bm, out, 0);
    // log_std path
    sgemm_nt_kernel<1><<<g2, blk>>>(BATCH, HID, 4 * HID, pX,  4 * HID, w21, 4 * HID, b21, pH1, HID);
    sgemm_nt_kernel<1><<<g2, blk>>>(BATCH, HID, HID,     pH1, HID,     w22, HID,     b22, pH2, HID);
    head_out_kernel<<<BATCH, blk>>>(pH2, ws, bs, out + (size_t)BATCH * NACT, 1);
}

// round 9
// speedup vs baseline: 1.4523x; 1.4523x over previous
#include <cuda_runtime.h>
#include <cstdint>

// ---------------------------------------------------------------------------
// GaussianPolicy forward — hybrid: fp32 SIMT phase-1 (bit-identical to the
// R1 passing run => identical spike decisions) + tf32 mma.sync heads.
//   B=2048, NIN=512, HID=1024, NACT=32, 5 frames repeated 3x -> 15 LIF steps.
// Heads (post-threshold, pure-rounding path):
//   L1: A = [count | count] (tf32-exact ints), B = tf32 2-split of (w/15)
//   L2: A = [t0|t1|t0] of relu(L1), B = [w0|w0|w1]   (3 products, ~2^-22)
// ---------------------------------------------------------------------------

namespace {
constexpr int BATCH = 2048, NIN = 512, HID = 1024, NACT = 32, FRAMES = 5;
// tf32 GEMM tiling
constexpr int BK     = 16;               // tf32 per k-chunk
constexpr int ROWB   = 80;               // 64B data + 16B pad per smem tile row
constexpr int TILEB  = 128 * ROWB;
constexpr int STAGEB = 2 * TILEB;
constexpr int NSTAGE = 3;
constexpr int SMEM_GEMM = NSTAGE * STAGEB;   // 61440 B
}

// ------------------------------ scratch (alloc-free rule) -------------------
__device__ __align__(256) float g_I   [(size_t)BATCH * FRAMES * 3 * HID];  // [b,f,j,h]
__device__ __align__(256) float g_Xc  [(size_t)BATCH * 2 * 4 * HID];       // [count|count]
__device__ __align__(256) float g_Wh1c[(size_t)2 * HID * 2 * 4 * HID];     // (w11|w21)/15 [w0,w1]
__device__ __align__(256) float g_bh1 [2 * HID];
__device__ __align__(256) float g_H1m [(size_t)BATCH * 3 * HID];           // [t0|t1|t0]
__device__ __align__(256) float g_H1s [(size_t)BATCH * 3 * HID];
__device__ __align__(256) float g_W12c[(size_t)HID * 3 * HID];             // [w0|w0|w1]
__device__ __align__(256) float g_W22c[(size_t)HID * 3 * HID];
__device__ __align__(256) float g_H2  [(size_t)BATCH * HID];

// ---------------------------------------------------------------------------
// Phase-1 SGEMM — VERBATIM from the R1 passing kernel (bit-identical g_I).
// C[M,N] = A[M,K] * W[N,K]^T + bias. 128x128 block, 8x8/thread, 256 threads.
// ---------------------------------------------------------------------------
template<int EPI>
__global__ void __launch_bounds__(256) sgemm_nt_kernel(
    int M, int N, int K,
    const float* __restrict__ A, int lda,
    const float* __restrict__ W, int ldb,
    const float* __restrict__ bias,
    float* __restrict__ C, int ldc)
{
    constexpr int BM = 128, BN = 128, BKs = 8, TM = 8, TN = 8;
    __shared__ float As[BKs][BM];
    __shared__ float Bs[BKs][BN];

    const int tid = threadIdx.x;
    const int bm  = blockIdx.y * BM;
    const int bn  = blockIdx.x * BN;
    const int tx  = tid & 15;
    const int ty  = tid >> 4;

    const int lrow = tid >> 1;
    const int lcol = (tid & 1) * 4;

    const float* Ablk = A + (size_t)bm * lda;
    const float* Bblk = W + (size_t)bn * ldb;

    float acc[TM][TN];
    #pragma unroll
    for (int i = 0; i < TM; i++)
        #pragma unroll
        for (int j = 0; j < TN; j++) acc[i][j] = 0.f;

    for (int k0 = 0; k0 < K; k0 += BKs) {
        float4 av = *(const float4*)(Ablk + (size_t)lrow * lda + k0 + lcol);
        float4 bv = *(const float4*)(Bblk + (size_t)lrow * ldb + k0 + lcol);
        As[lcol + 0][lrow] = av.x; As[lcol + 1][lrow] = av.y;
        As[lcol + 2][lrow] = av.z; As[lcol + 3][lrow] = av.w;
        Bs[lcol + 0][lrow] = bv.x; Bs[lcol + 1][lrow] = bv.y;
        Bs[lcol + 2][lrow] = bv.z; Bs[lcol + 3][lrow] = bv.w;
        __syncthreads();

        #pragma unroll
        for (int k = 0; k < BKs; k++) {
            float ar[TM], br[TN];
            float4 t;
            t = *(const float4*)&As[k][ty * TM];     ar[0]=t.x; ar[1]=t.y; ar[2]=t.z; ar[3]=t.w;
            t = *(const float4*)&As[k][ty * TM + 4]; ar[4]=t.x; ar[5]=t.y; ar[6]=t.z; ar[7]=t.w;
            t = *(const float4*)&Bs[k][tx * TN];     br[0]=t.x; br[1]=t.y; br[2]=t.z; br[3]=t.w;
            t = *(const float4*)&Bs[k][tx * TN + 4]; br[4]=t.x; br[5]=t.y; br[6]=t.z; br[7]=t.w;
            #pragma unroll
            for (int i = 0; i < TM; i++)
                #pragma unroll
                for (int j = 0; j < TN; j++)
                    acc[i][j] = fmaf(ar[i], br[j], acc[i][j]);
        }
        __syncthreads();
    }

    #pragma unroll
    for (int i = 0; i < TM; i++) {
        const int row = bm + ty * TM + i;
        #pragma unroll
        for (int j = 0; j < TN; j++) {
            const int col = bn + tx * TN + j;
            float v = acc[i][j] + bias[col];
            if (EPI == 1) v = fmaxf(v, 0.f);
            C[(size_t)row * ldc + col] = v;
        }
    }
}

// ------------------------------ PTX helpers (tf32 path) ---------------------
__device__ __forceinline__ uint32_t smem_u32(const void* p) {
    uint32_t a;
    asm("{ .reg .u64 t; cvta.to.shared.u64 t, %1; cvt.u32.u64 %0, t; }" : "=r"(a) : "l"(p));
    return a;
}
__device__ __forceinline__ void cpasync16(uint32_t dst, const void* src) {
    asm volatile("cp.async.cg.shared.global [%0], [%1], 16;" :: "r"(dst), "l"(src));
}
__device__ __forceinline__ void cp_commit() {
    asm volatile("cp.async.commit_group;" ::: "memory");
}
template<int N> __device__ __forceinline__ void cp_wait() {
    asm volatile("cp.async.wait_group %0;" :: "n"(N) : "memory");
}
__device__ __forceinline__ void lds32(uint32_t& r, uint32_t addr) {
    asm volatile("ld.shared.b32 %0, [%1];" : "=r"(r) : "r"(addr));
}
__device__ __forceinline__ void mma_tf32(float* d, const uint32_t* a, uint32_t b0, uint32_t b1) {
    asm volatile(
        "mma.sync.aligned.m16n8k8.row.col.f32.tf32.tf32.f32 "
        "{%0,%1,%2,%3}, {%4,%5,%6,%7}, {%8,%9}, {%0,%1,%2,%3};"
        : "+f"(d[0]), "+f"(d[1]), "+f"(d[2]), "+f"(d[3])
        : "r"(a[0]), "r"(a[1]), "r"(a[2]), "r"(a[3]), "r"(b0), "r"(b1));
}
__device__ __forceinline__ void tf32_split(float v, float& t0, float& t1) {
    uint32_t u0, u1;
    asm("cvt.rna.tf32.f32 %0, %1;" : "=r"(u0) : "f"(v));
    float f0 = __uint_as_float(u0);
    float r = v - f0;
    asm("cvt.rna.tf32.f32 %0, %1;" : "=r"(u1) : "f"(r));
    t0 = f0;
    t1 = __uint_as_float(u1);
}

// ---------------------------------------------------------------------------
// NT tf32 GEMM: C[M,N] = A[M,K]*B[N,K]^T (+bias, epilogues).
// EPI 1: relu fp32.  EPI 2: relu -> tf32 [t0|t1|t0] into O0(col<HID)/O1.
// 128x128x16 tile, 8 warps (2x4), warp tile 64x32, 3-stage cp.async pipeline.
// ---------------------------------------------------------------------------
template<int EPI>
__global__ void __launch_bounds__(256, 2) gemm_tf32(
    int M, int N, int K,
    const float* __restrict__ A, const float* __restrict__ B,
    const float* __restrict__ bias,
    float* __restrict__ C, int ldc,
    float* __restrict__ O0, float* __restrict__ O1)
{
    extern __shared__ char smem[];
    const uint32_t sbase = smem_u32(smem);
    const int tid = threadIdx.x;
    const int lane = tid & 31, w = tid >> 5;
    const int wm = w >> 2, wn = w & 3;
    const int bm = blockIdx.y * 128, bn = blockIdx.x * 128;

    float acc[4][4][4];
    #pragma unroll
    for (int i = 0; i < 4; i++)
        #pragma unroll
        for (int j = 0; j < 4; j++)
            #pragma unroll
            for (int k = 0; k < 4; k++) acc[i][j][k] = 0.f;

    const int nch = K / BK;

    auto issue_loads = [&](int s, int c) {
        const int kc = c * BK;
        const uint32_t base = sbase + s * STAGEB;
        #pragma unroll
        for (int t = 0; t < 4; t++) {
            const int idx = t * 256 + tid;
            const int isB = idx >> 9;
            const int r   = (idx >> 2) & 127;
            const int g   = idx & 3;
            const float* src = (isB ? B + (size_t)(bn + r) * K
                                    : A + (size_t)(bm + r) * K) + kc + g * 4;
            cpasync16(base + isB * TILEB + (uint32_t)(r * ROWB + g * 16), src);
        }
    };
    auto compute_stage = [&](int s) {
        const uint32_t sa = sbase + s * STAGEB + (uint32_t)(wm * 64) * ROWB;
        const uint32_t sb = sbase + s * STAGEB + TILEB + (uint32_t)(wn * 32) * ROWB;
        const int g = lane >> 2, t = lane & 3;
        #pragma unroll
        for (int ks = 0; ks < 2; ks++) {
            uint32_t a[4][4], b[4][2];
            #pragma unroll
            for (int ma = 0; ma < 4; ma++) {
                const uint32_t r0 = sa + (uint32_t)((ma * 16 + g) * ROWB + (ks * 8 + t) * 4);
                const uint32_t r1 = r0 + 8 * ROWB;
                lds32(a[ma][0], r0);
                lds32(a[ma][1], r1);
                lds32(a[ma][2], r0 + 16);
                lds32(a[ma][3], r1 + 16);
            }
            #pragma unroll
            for (int na = 0; na < 4; na++) {
                const uint32_t rb = sb + (uint32_t)((na * 8 + g) * ROWB + (ks * 8 + t) * 4);
                lds32(b[na][0], rb);
                lds32(b[na][1], rb + 16);
            }
            #pragma unroll
            for (int ma = 0; ma < 4; ma++)
                #pragma unroll
                for (int na = 0; na < 4; na++)
                    mma_tf32(acc[ma][na], a[ma], b[na][0], b[na][1]);
        }
    };

    #pragma unroll
    for (int c = 0; c < NSTAGE; c++) {
        if (c < nch) issue_loads(c, c);
        cp_commit();
    }
    for (int c = 0; c < nch; c++) {
        const int s = c % NSTAGE;
        cp_wait<NSTAGE - 1>();
        __syncthreads();
        compute_stage(s);
        __syncthreads();
        if (c + NSTAGE < nch) issue_loads(s, c + NSTAGE);
        cp_commit();
    }

    const int r0b  = bm + wm * 64 + (lane >> 2);
    const int colb = bn + wn * 32 + (lane & 3) * 2;
    #pragma unroll
    for (int ma = 0; ma < 4; ma++) {
        const int r0 = r0b + ma * 16;
        #pragma unroll
        for (int na = 0; na < 4; na++) {
            const int col = colb + na * 8;
            const float bv0 = bias[col], bv1 = bias[col + 1];
            float v00 = acc[ma][na][0] + bv0, v01 = acc[ma][na][1] + bv1;
            float v10 = acc[ma][na][2] + bv0, v11 = acc[ma][na][3] + bv1;
            v00 = fmaxf(v00, 0.f); v01 = fmaxf(v01, 0.f);
            v10 = fmaxf(v10, 0.f); v11 = fmaxf(v11, 0.f);
            if (EPI == 1) {
                *(float2*)&C[(size_t)r0 * ldc + col]       = make_float2(v00, v01);
                *(float2*)&C[(size_t)(r0 + 8) * ldc + col] = make_float2(v10, v11);
            } else {
                float* buf = (col < HID) ? O0 : O1;
                const int cc = col & (HID - 1);
                #pragma unroll
                for (int hr = 0; hr < 2; hr++) {
                    const int rr = r0 + hr * 8;
                    const float u0 = hr ? v10 : v00;
                    const float u1 = hr ? v11 : v01;
                    float t00, t01, t10, t11;
                    tf32_split(u0, t00, t01);
                    tf32_split(u1, t10, t11);
                    float* p = buf + (size_t)rr * (3 * HID) + cc;
                    p[0]           = t00;  p[1]           = t10;
                    p[HID]         = t01;  p[HID + 1]     = t11;
                    p[2 * HID]     = t00;  p[2 * HID + 1] = t10;
                }
            }
        }
    }
}

// ------------------------------ split kernels -------------------------------
// Head-L1 weights: w*scale -> [w0, w1]
__global__ void __launch_bounds__(256) split_tf32_B2_scaled(
    const float* __restrict__ in, float* __restrict__ out, float scale, int K, int n)
{
    int i = blockIdx.x * 256 + threadIdx.x;
    if (i >= n) return;
    int r = i / K, k = i - r * K;
    float t0, t1;
    tf32_split(in[i] * scale, t0, t1);
    float* p = out + (size_t)r * 2 * K + k;
    p[0] = t0; p[K] = t1;
}
// Head-L2 weights: [w0, w0, w1]
__global__ void __launch_bounds__(256) split_tf32_B(
    const float* __restrict__ in, float* __restrict__ out, int K, int n)
{
    int i = blockIdx.x * 256 + threadIdx.x;
    if (i >= n) return;
    int r = i / K, k = i - r * K;
    float t0, t1;
    tf32_split(in[i], t0, t1);
    float* p = out + (size_t)r * 3 * K + k;
    p[0] = t0; p[K] = t0; p[2 * K] = t1;
}

// ------------------------------ LIF scan ------------------------------------
// Exact reference semantics; writes spike counts (tf32-exact ints) duplicated
// into Xc [B, 2*4096] = [count | count].
__global__ void __launch_bounds__(256) scan_kernel(
    const float* __restrict__ I,   // [b, f, j, h]
    const float* __restrict__ wl, const float* __restrict__ bl,
    float* __restrict__ Xc)
{
    const int idx = blockIdx.x * 256 + threadIdx.x;
    const int b = idx >> 10;
    const int h = idx & (HID - 1);
    if (b >= BATCH) return;

    const float wl0 = wl[0], wl1 = wl[1], wl2 = wl[2], blv = bl[0];
    float m0 = 0.f, m1 = 0.f, m2 = 0.f, m3 = 0.f;
    float s0 = 0.f, s1 = 0.f, s2 = 0.f, s3 = 0.f;
    float a0 = 0.f, a1 = 0.f, a2 = 0.f, a3 = 0.f;

    const float* Ib = I + (size_t)b * FRAMES * 3 * HID + h;
    #pragma unroll
    for (int f = 0; f < FRAMES; f++) {
        const float i1 = Ib[(f * 3 + 0) * HID];
        const float i2 = Ib[(f * 3 + 1) * HID];
        const float i3 = Ib[(f * 3 + 2) * HID];
        #pragma unroll
        for (int r = 0; r < 3; r++) {
            const float inner = fmaf(m0, wl0, fmaf(m1, wl1, fmaf(m2, wl2, blv)));
            m0 = (m0 * 0.2f) * (1.f - s0) + i1;
            m1 = (m1 * 0.2f) * (1.f - s1) + i2;
            m2 = (m2 * 0.2f) * (1.f - s2) + i3;
            m3 = (m3 * 0.2f) * (1.f - s3) + inner;
            s0 = (m0 > 0.8f) ? 1.f : 0.f;
            s1 = (m1 > 0.8f) ? 1.f : 0.f;
            s2 = (m2 > 0.8f) ? 1.f : 0.f;
            s3 = (m3 > 0.8f) ? 1.f : 0.f;
            a0 += s0; a1 += s1; a2 += s2; a3 += s3;
        }
    }
    float4 v = make_float4(a0, a1, a2, a3);
    const size_t ob = (size_t)b * (2 * 4 * HID) + h * 4;
    *(float4*)(Xc + ob)           = v;
    *(float4*)(Xc + ob + 4 * HID) = v;
}

// ------------------------------ tiny output layer ---------------------------
__global__ void __launch_bounds__(256) head_out_kernel(
    const float* __restrict__ X, const float* __restrict__ W,
    const float* __restrict__ bias, float* __restrict__ out, int doclip)
{
    __shared__ float xs[HID];
    const int b = blockIdx.x;
    const float* xrow = X + (size_t)b * HID;
    for (int i = threadIdx.x; i < HID; i += 256) xs[i] = xrow[i];
    __syncthreads();

    const int warp = threadIdx.x >> 5;
    const int lane = threadIdx.x & 31;
    for (int o = warp; o < NACT; o += 8) {
        const float* wrow = W + (size_t)o * HID;
        float acc = 0.f;
        #pragma unroll 4
        for (int k = lane; k < HID; k += 32)
            acc = fmaf(xs[k], wrow[k], acc);
        #pragma unroll
        for (int s = 16; s > 0; s >>= 1)
            acc += __shfl_xor_sync(0xffffffff, acc, s);
        if (lane == 0) {
            float v = acc + bias[o];
            if (doclip) v = fminf(fmaxf(v, -20.f), 2.f);
            out[(size_t)b * NACT + o] = v;
        }
    }
}

// ---------------------------------------------------------------------------
extern "C" void kernel_launch(void* const* d_in, const int* in_sizes, int n_in,
                              void* d_out, int out_size)
{
    const float* state = (const float*)d_in[0];
    const float* w1  = (const float*)d_in[1];  const float* b1  = (const float*)d_in[2];
    const float* w2  = (const float*)d_in[3];  const float* b2  = (const float*)d_in[4];
    const float* w3  = (const float*)d_in[5];  const float* b3  = (const float*)d_in[6];
    const float* wl  = (const float*)d_in[7];  const float* bl  = (const float*)d_in[8];
    const float* w11 = (const float*)d_in[9];  const float* b11 = (const float*)d_in[10];
    const float* w12 = (const float*)d_in[11]; const float* b12 = (const float*)d_in[12];
    const float* w21 = (const float*)d_in[13]; const float* b21 = (const float*)d_in[14];
    const float* w22 = (const float*)d_in[15]; const float* b22 = (const float*)d_in[16];
    const float* wm  = (const float*)d_in[17]; const float* bm  = (const float*)d_in[18];
    const float* ws  = (const float*)d_in[19]; const float* bs  = (const float*)d_in[20];
    float* out = (float*)d_out;

    float *pI, *pXc, *pWh1c, *pBh1, *pH1m, *pH1s, *pW12c, *pW22c, *pH2;
    cudaGetSymbolAddress((void**)&pI,    g_I);
    cudaGetSymbolAddress((void**)&pXc,   g_Xc);
    cudaGetSymbolAddress((void**)&pWh1c, g_Wh1c);
    cudaGetSymbolAddress((void**)&pBh1,  g_bh1);
    cudaGetSymbolAddress((void**)&pH1m,  g_H1m);
    cudaGetSymbolAddress((void**)&pH1s,  g_H1s);
    cudaGetSymbolAddress((void**)&pW12c, g_W12c);
    cudaGetSymbolAddress((void**)&pW22c, g_W22c);
    cudaGetSymbolAddress((void**)&pH2,   g_H2);

    cudaFuncSetAttribute(gemm_tf32<1>, cudaFuncAttributeMaxDynamicSharedMemorySize, SMEM_GEMM);
    cudaFuncSetAttribute(gemm_tf32<2>, cudaFuncAttributeMaxDynamicSharedMemorySize, SMEM_GEMM);

    const dim3 blk(256);

    // ---- weight prep for tf32 heads ----
    {
        int n = HID * 4 * HID;
        split_tf32_B2_scaled<<<(n + 255) / 256, blk>>>(w11, pWh1c, 1.f / 15.f, 4 * HID, n);
        split_tf32_B2_scaled<<<(n + 255) / 256, blk>>>(w21, pWh1c + (size_t)HID * 2 * 4 * HID,
                                                       1.f / 15.f, 4 * HID, n);
        n = HID * HID;
        split_tf32_B<<<(n + 255) / 256, blk>>>(w12, pW12c, HID, n);
        split_tf32_B<<<(n + 255) / 256, blk>>>(w22, pW22c, HID, n);
        cudaMemcpyAsync(pBh1,       b11, HID * 4, cudaMemcpyDeviceToDevice);
        cudaMemcpyAsync(pBh1 + HID, b21, HID * 4, cudaMemcpyDeviceToDevice);
    }

    // ---- phase 1: 3 fp32 SIMT GEMMs (bit-identical to R1 pass) ----
    {
        const dim3 g1(HID / 128, (BATCH * FRAMES) / 128);
        sgemm_nt_kernel<0><<<g1, blk>>>(BATCH * FRAMES, HID, NIN, state, NIN, w1, NIN, b1, pI + 0 * HID, 3 * HID);
        sgemm_nt_kernel<0><<<g1, blk>>>(BATCH * FRAMES, HID, NIN, state, NIN, w2, NIN, b2, pI + 1 * HID, 3 * HID);
        sgemm_nt_kernel<0><<<g1, blk>>>(BATCH * FRAMES, HID, NIN, state, NIN, w3, NIN, b3, pI + 2 * HID, 3 * HID);
    }

    // ---- phase 2: LIF scan -> duplicated exact counts ----
    scan_kernel<<<(BATCH * HID) / 256, blk>>>(pI, wl, bl, pXc);

    // ---- phase 3: heads on tf32 tensor pipe ----
    {   // layer 1, both heads stacked along N (K'=8192)
        const dim3 g(2 * HID / 128, BATCH / 128);
        gemm_tf32<2><<<g, blk, SMEM_GEMM>>>(BATCH, 2 * HID, 2 * 4 * HID,
            pXc, pWh1c, pBh1, nullptr, 0, pH1m, pH1s);
    }
    {   // layer 2 + output (K'=3072)
        const dim3 g(HID / 128, BATCH / 128);
        gemm_tf32<1><<<g, blk, SMEM_GEMM>>>(BATCH, HID, 3 * HID,
            pH1m, pW12c, b12, pH2, HID, nullptr, nullptr);
        head_out_kernel<<<BATCH, blk>>>(pH2, wm, bm, out, 0);
        gemm_tf32<1><<<g, blk, SMEM_GEMM>>>(BATCH, HID, 3 * HID,
            pH1s, pW22c, b22, pH2, HID, nullptr, nullptr);
        head_out_kernel<<<BATCH, blk>>>(pH2, ws, bs, out + (size_t)BATCH * NACT, 1);
    }
}

// round 12
// speedup vs baseline: 1.6624x; 1.1447x over previous
#include <cuda_runtime.h>
#include <cstdint>

// ---------------------------------------------------------------------------
// GaussianPolicy forward — tf32 phase-1 with flag-and-repair.
//   B=2048, NIN=512, HID=1024, NACT=32, 5 frames repeated 3x -> 15 LIF steps.
// Numerics contract: output is bitwise identical to the R9 passing run.
//   phase 1: tf32 3-product GEMM (err ~4e-6 abs). Lanes whose LIF membrane
//     ever comes within EPS=3e-5 of the 0.8 threshold are REPAIRED: their 15
//     input currents are recomputed with serial fmaf (bitwise = R9's sgemm)
//     and the LIF rerun. Unflagged lanes: deviation << EPS cannot change any
//     spike vs the sgemm-I trajectory (inductive same-side guarantee).
//   heads: tf32 mma (unchanged from R9; pure-rounding path, err 2.75e-5).
// ---------------------------------------------------------------------------

namespace {
constexpr int BATCH = 2048, NIN = 512, HID = 1024, NACT = 32, FRAMES = 5;
constexpr int BK     = 16;
constexpr int ROWB   = 80;
constexpr int TILEB  = 128 * ROWB;
constexpr int STAGEB = 2 * TILEB;
constexpr int NSTAGE = 3;
constexpr int SMEM_GEMM = NSTAGE * STAGEB;   // 61440 B
constexpr int MAXFLAG = 262144;              // ~100x expected flag count
constexpr float EPS = 3e-5f;
}

// ------------------------------ scratch (alloc-free rule) -------------------
__device__ __align__(256) float g_I    [(size_t)BATCH * FRAMES * 3 * HID];  // [b,f,j,h]
__device__ __align__(256) float g_Ac   [(size_t)BATCH * FRAMES * 3 * NIN];  // state [t0,t1,t0]
__device__ __align__(256) float g_W123c[(size_t)3 * HID * 3 * NIN];         // w1|w2|w3 [w0,w0,w1]
__device__ __align__(256) float g_b123 [3 * HID];
__device__ __align__(256) float g_Xc   [(size_t)BATCH * 2 * 4 * HID];       // [count|count]
__device__ __align__(256) float g_Wh1c [(size_t)2 * HID * 2 * 4 * HID];     // (w11|w21)/15 [w0,w1]
__device__ __align__(256) float g_bh1  [2 * HID];
__device__ __align__(256) float g_H1m  [(size_t)BATCH * 3 * HID];
__device__ __align__(256) float g_H1s  [(size_t)BATCH * 3 * HID];
__device__ __align__(256) float g_W12c [(size_t)HID * 3 * HID];
__device__ __align__(256) float g_W22c [(size_t)HID * 3 * HID];
__device__ __align__(256) float g_H2   [(size_t)BATCH * HID];
__device__ __align__(256) int   g_flag [MAXFLAG];
__device__              int     g_cnt;
__device__ __align__(256) float g_Irep [(size_t)MAXFLAG * 15];

// ------------------------------ PTX helpers ---------------------------------
__device__ __forceinline__ uint32_t smem_u32(const void* p) {
    uint32_t a;
    asm("{ .reg .u64 t; cvta.to.shared.u64 t, %1; cvt.u32.u64 %0, t; }" : "=r"(a) : "l"(p));
    return a;
}
__device__ __forceinline__ void cpasync16(uint32_t dst, const void* src) {
    asm volatile("cp.async.cg.shared.global [%0], [%1], 16;" :: "r"(dst), "l"(src));
}
__device__ __forceinline__ void cp_commit() {
    asm volatile("cp.async.commit_group;" ::: "memory");
}
template<int N> __device__ __forceinline__ void cp_wait() {
    asm volatile("cp.async.wait_group %0;" :: "n"(N) : "memory");
}
__device__ __forceinline__ void lds32(uint32_t& r, uint32_t addr) {
    asm volatile("ld.shared.b32 %0, [%1];" : "=r"(r) : "r"(addr));
}
__device__ __forceinline__ void mma_tf32(float* d, const uint32_t* a, uint32_t b0, uint32_t b1) {
    asm volatile(
        "mma.sync.aligned.m16n8k8.row.col.f32.tf32.tf32.f32 "
        "{%0,%1,%2,%3}, {%4,%5,%6,%7}, {%8,%9}, {%0,%1,%2,%3};"
        : "+f"(d[0]), "+f"(d[1]), "+f"(d[2]), "+f"(d[3])
        : "r"(a[0]), "r"(a[1]), "r"(a[2]), "r"(a[3]), "r"(b0), "r"(b1));
}
__device__ __forceinline__ void tf32_split(float v, float& t0, float& t1) {
    uint32_t u0, u1;
    asm("cvt.rna.tf32.f32 %0, %1;" : "=r"(u0) : "f"(v));
    float f0 = __uint_as_float(u0);
    float r = v - f0;
    asm("cvt.rna.tf32.f32 %0, %1;" : "=r"(u1) : "f"(r));
    t0 = f0;
    t1 = __uint_as_float(u1);
}

// ---------------------------------------------------------------------------
// NT tf32 GEMM (identical engine to R9).
// EPI 0: bias fp32. EPI 1: relu fp32. EPI 2: relu -> [t0|t1|t0] split out.
// ---------------------------------------------------------------------------
template<int EPI>
__global__ void __launch_bounds__(256, 2) gemm_tf32(
    int M, int N, int K,
    const float* __restrict__ A, const float* __restrict__ B,
    const float* __restrict__ bias,
    float* __restrict__ C, int ldc,
    float* __restrict__ O0, float* __restrict__ O1)
{
    extern __shared__ char smem[];
    const uint32_t sbase = smem_u32(smem);
    const int tid = threadIdx.x;
    const int lane = tid & 31, w = tid >> 5;
    const int wm = w >> 2, wn = w & 3;
    const int bm = blockIdx.y * 128, bn = blockIdx.x * 128;

    float acc[4][4][4];
    #pragma unroll
    for (int i = 0; i < 4; i++)
        #pragma unroll
        for (int j = 0; j < 4; j++)
            #pragma unroll
            for (int k = 0; k < 4; k++) acc[i][j][k] = 0.f;

    const int nch = K / BK;

    auto issue_loads = [&](int s, int c) {
        const int kc = c * BK;
        const uint32_t base = sbase + s * STAGEB;
        #pragma unroll
        for (int t = 0; t < 4; t++) {
            const int idx = t * 256 + tid;
            const int isB = idx >> 9;
            const int r   = (idx >> 2) & 127;
            const int g   = idx & 3;
            const float* src = (isB ? B + (size_t)(bn + r) * K
                                    : A + (size_t)(bm + r) * K) + kc + g * 4;
            cpasync16(base + isB * TILEB + (uint32_t)(r * ROWB + g * 16), src);
        }
    };
    auto compute_stage = [&](int s) {
        const uint32_t sa = sbase + s * STAGEB + (uint32_t)(wm * 64) * ROWB;
        const uint32_t sb = sbase + s * STAGEB + TILEB + (uint32_t)(wn * 32) * ROWB;
        const int g = lane >> 2, t = lane & 3;
        #pragma unroll
        for (int ks = 0; ks < 2; ks++) {
            uint32_t a[4][4], b[4][2];
            #pragma unroll
            for (int ma = 0; ma < 4; ma++) {
                const uint32_t r0 = sa + (uint32_t)((ma * 16 + g) * ROWB + (ks * 8 + t) * 4);
                const uint32_t r1 = r0 + 8 * ROWB;
                lds32(a[ma][0], r0);
                lds32(a[ma][1], r1);
                lds32(a[ma][2], r0 + 16);
                lds32(a[ma][3], r1 + 16);
            }
            #pragma unroll
            for (int na = 0; na < 4; na++) {
                const uint32_t rb = sb + (uint32_t)((na * 8 + g) * ROWB + (ks * 8 + t) * 4);
                lds32(b[na][0], rb);
                lds32(b[na][1], rb + 16);
            }
            #pragma unroll
            for (int ma = 0; ma < 4; ma++)
                #pragma unroll
                for (int na = 0; na < 4; na++)
                    mma_tf32(acc[ma][na], a[ma], b[na][0], b[na][1]);
        }
    };

    #pragma unroll
    for (int c = 0; c < NSTAGE; c++) {
        if (c < nch) issue_loads(c, c);
        cp_commit();
    }
    for (int c = 0; c < nch; c++) {
        const int s = c % NSTAGE;
        cp_wait<NSTAGE - 1>();
        __syncthreads();
        compute_stage(s);
        __syncthreads();
        if (c + NSTAGE < nch) issue_loads(s, c + NSTAGE);
        cp_commit();
    }

    const int r0b  = bm + wm * 64 + (lane >> 2);
    const int colb = bn + wn * 32 + (lane & 3) * 2;
    #pragma unroll
    for (int ma = 0; ma < 4; ma++) {
        const int r0 = r0b + ma * 16;
        #pragma unroll
        for (int na = 0; na < 4; na++) {
            const int col = colb + na * 8;
            const float bv0 = bias[col], bv1 = bias[col + 1];
            float v00 = acc[ma][na][0] + bv0, v01 = acc[ma][na][1] + bv1;
            float v10 = acc[ma][na][2] + bv0, v11 = acc[ma][na][3] + bv1;
            if (EPI >= 1) {
                v00 = fmaxf(v00, 0.f); v01 = fmaxf(v01, 0.f);
                v10 = fmaxf(v10, 0.f); v11 = fmaxf(v11, 0.f);
            }
            if (EPI <= 1) {
                *(float2*)&C[(size_t)r0 * ldc + col]       = make_float2(v00, v01);
                *(float2*)&C[(size_t)(r0 + 8) * ldc + col] = make_float2(v10, v11);
            } else {
                float* buf = (col < HID) ? O0 : O1;
                const int cc = col & (HID - 1);
                #pragma unroll
                for (int hr = 0; hr < 2; hr++) {
                    const int rr = r0 + hr * 8;
                    const float u0 = hr ? v10 : v00;
                    const float u1 = hr ? v11 : v01;
                    float t00, t01, t10, t11;
                    tf32_split(u0, t00, t01);
                    tf32_split(u1, t10, t11);
                    float* p = buf + (size_t)rr * (3 * HID) + cc;
                    p[0]           = t00;  p[1]           = t10;
                    p[HID]         = t01;  p[HID + 1]     = t11;
                    p[2 * HID]     = t00;  p[2 * HID + 1] = t10;
                }
            }
        }
    }
}

// ------------------------------ split kernels -------------------------------
__global__ void __launch_bounds__(256) split_tf32_A(
    const float* __restrict__ in, float* __restrict__ out, int K, int n)
{
    int i = blockIdx.x * 256 + threadIdx.x;
    if (i >= n) return;
    int r = i / K, k = i - r * K;
    float t0, t1;
    tf32_split(in[i], t0, t1);
    float* p = out + (size_t)r * 3 * K + k;
    p[0] = t0; p[K] = t1; p[2 * K] = t0;
}
__global__ void __launch_bounds__(256) split_tf32_B(
    const float* __restrict__ in, float* __restrict__ out, int K, int n)
{
    int i = blockIdx.x * 256 + threadIdx.x;
    if (i >= n) return;
    int r = i / K, k = i - r * K;
    float t0, t1;
    tf32_split(in[i], t0, t1);
    float* p = out + (size_t)r * 3 * K + k;
    p[0] = t0; p[K] = t0; p[2 * K] = t1;
}
__global__ void __launch_bounds__(256) split_tf32_B2_scaled(
    const float* __restrict__ in, float* __restrict__ out, float scale, int K, int n)
{
    int i = blockIdx.x * 256 + threadIdx.x;
    if (i >= n) return;
    int r = i / K, k = i - r * K;
    float t0, t1;
    tf32_split(in[i] * scale, t0, t1);
    float* p = out + (size_t)r * 2 * K + k;
    p[0] = t0; p[K] = t1;
}

// ------------------------------ LIF scan + flag ------------------------------
__global__ void __launch_bounds__(256) scan_flag_kernel(
    const float* __restrict__ I,   // [b, f, j, h]  (tf32-GEMM result)
    const float* __restrict__ wl, const float* __restrict__ bl,
    float* __restrict__ Xc, int* __restrict__ flags, int* __restrict__ cnt)
{
    const int idx = blockIdx.x * 256 + threadIdx.x;
    const int b = idx >> 10;
    const int h = idx & (HID - 1);
    if (b >= BATCH) return;

    const float wl0 = wl[0], wl1 = wl[1], wl2 = wl[2], blv = bl[0];
    float m0 = 0.f, m1 = 0.f, m2 = 0.f, m3 = 0.f;
    float s0 = 0.f, s1 = 0.f, s2 = 0.f, s3 = 0.f;
    float a0 = 0.f, a1 = 0.f, a2 = 0.f, a3 = 0.f;
    float gap = 1e30f;

    const float* Ib = I + (size_t)b * FRAMES * 3 * HID + h;
    #pragma unroll
    for (int f = 0; f < FRAMES; f++) {
        const float i1 = Ib[(f * 3 + 0) * HID];
        const float i2 = Ib[(f * 3 + 1) * HID];
        const float i3 = Ib[(f * 3 + 2) * HID];
        #pragma unroll
        for (int r = 0; r < 3; r++) {
            const float inner = fmaf(m0, wl0, fmaf(m1, wl1, fmaf(m2, wl2, blv)));
            m0 = (m0 * 0.2f) * (1.f - s0) + i1;
            m1 = (m1 * 0.2f) * (1.f - s1) + i2;
            m2 = (m2 * 0.2f) * (1.f - s2) + i3;
            m3 = (m3 * 0.2f) * (1.f - s3) + inner;
            gap = fminf(gap, fabsf(m0 - 0.8f));
            gap = fminf(gap, fabsf(m1 - 0.8f));
            gap = fminf(gap, fabsf(m2 - 0.8f));
            gap = fminf(gap, fabsf(m3 - 0.8f));
            s0 = (m0 > 0.8f) ? 1.f : 0.f;
            s1 = (m1 > 0.8f) ? 1.f : 0.f;
            s2 = (m2 > 0.8f) ? 1.f : 0.f;
            s3 = (m3 > 0.8f) ? 1.f : 0.f;
            a0 += s0; a1 += s1; a2 += s2; a3 += s3;
        }
    }
    if (gap < EPS) {
        int slot = atomicAdd(cnt, 1);
        if (slot < MAXFLAG) flags[slot] = idx;
    }
    float4 v = make_float4(a0, a1, a2, a3);
    const size_t ob = (size_t)b * (2 * 4 * HID) + h * 4;
    *(float4*)(Xc + ob)           = v;
    *(float4*)(Xc + ob + 4 * HID) = v;
}

// ------------------------------ repair --------------------------------------
// Recompute the 15 input currents of a flagged lane with serial fmaf
// (bitwise identical to the R9 sgemm accumulation: acc over k asc, then +bias).
__global__ void __launch_bounds__(256) repair_dots_kernel(
    const float* __restrict__ state,
    const float* __restrict__ w1, const float* __restrict__ b1,
    const float* __restrict__ w2, const float* __restrict__ b2,
    const float* __restrict__ w3, const float* __restrict__ b3,
    const int* __restrict__ flags, const int* __restrict__ cnt,
    float* __restrict__ Irep)
{
    const int idx = blockIdx.x * 256 + threadIdx.x;
    const int lane_i = idx / 15;
    const int t = idx - lane_i * 15;
    const int n = min(*cnt, MAXFLAG);
    if (lane_i >= n) return;
    const int bh = flags[lane_i];
    const int b = bh >> 10, h = bh & (HID - 1);
    const int f = t / 3, j = t - f * 3;

    const float* a = state + ((size_t)b * FRAMES + f) * NIN;
    const float* wv = (j == 0 ? w1 : (j == 1 ? w2 : w3)) + (size_t)h * NIN;
    const float* bv = (j == 0 ? b1 : (j == 1 ? b2 : b3));
    float acc = 0.f;
    for (int k = 0; k < NIN; k++)
        acc = fmaf(a[k], wv[k], acc);
    Irep[(size_t)lane_i * 15 + t] = acc + bv[h];
}

__global__ void __launch_bounds__(256) repair_scan_kernel(
    const float* __restrict__ Irep,
    const float* __restrict__ wl, const float* __restrict__ bl,
    const int* __restrict__ flags, const int* __restrict__ cnt,
    float* __restrict__ Xc)
{
    const int lane_i = blockIdx.x * 256 + threadIdx.x;
    const int n = min(*cnt, MAXFLAG);
    if (lane_i >= n) return;
    const int bh = flags[lane_i];
    const int b = bh >> 10, h = bh & (HID - 1);

    const float wl0 = wl[0], wl1 = wl[1], wl2 = wl[2], blv = bl[0];
    float m0 = 0.f, m1 = 0.f, m2 = 0.f, m3 = 0.f;
    float s0 = 0.f, s1 = 0.f, s2 = 0.f, s3 = 0.f;
    float a0 = 0.f, a1 = 0.f, a2 = 0.f, a3 = 0.f;

    const float* Ib = Irep + (size_t)lane_i * 15;
    #pragma unroll
    for (int f = 0; f < FRAMES; f++) {
        const float i1 = Ib[f * 3 + 0];
        const float i2 = Ib[f * 3 + 1];
        const float i3 = Ib[f * 3 + 2];
        #pragma unroll
        for (int r = 0; r < 3; r++) {
            const float inner = fmaf(m0, wl0, fmaf(m1, wl1, fmaf(m2, wl2, blv)));
            m0 = (m0 * 0.2f) * (1.f - s0) + i1;
            m1 = (m1 * 0.2f) * (1.f - s1) + i2;
            m2 = (m2 * 0.2f) * (1.f - s2) + i3;
            m3 = (m3 * 0.2f) * (1.f - s3) + inner;
            s0 = (m0 > 0.8f) ? 1.f : 0.f;
            s1 = (m1 > 0.8f) ? 1.f : 0.f;
            s2 = (m2 > 0.8f) ? 1.f : 0.f;
            s3 = (m3 > 0.8f) ? 1.f : 0.f;
            a0 += s0; a1 += s1; a2 += s2; a3 += s3;
        }
    }
    float4 v = make_float4(a0, a1, a2, a3);
    const size_t ob = (size_t)b * (2 * 4 * HID) + h * 4;
    *(float4*)(Xc + ob)           = v;
    *(float4*)(Xc + ob + 4 * HID) = v;
}

// ------------------------------ tiny output layer ---------------------------
__global__ void __launch_bounds__(256) head_out_kernel(
    const float* __restrict__ X, const float* __restrict__ W,
    const float* __restrict__ bias, float* __restrict__ out, int doclip)
{
    __shared__ float xs[HID];
    const int b = blockIdx.x;
    const float* xrow = X + (size_t)b * HID;
    for (int i = threadIdx.x; i < HID; i += 256) xs[i] = xrow[i];
    __syncthreads();

    const int warp = threadIdx.x >> 5;
    const int lane = threadIdx.x & 31;
    for (int o = warp; o < NACT; o += 8) {
        const float* wrow = W + (size_t)o * HID;
        float acc = 0.f;
        #pragma unroll 4
        for (int k = lane; k < HID; k += 32)
            acc = fmaf(xs[k], wrow[k], acc);
        #pragma unroll
        for (int s = 16; s > 0; s >>= 1)
            acc += __shfl_xor_sync(0xffffffff, acc, s);
        if (lane == 0) {
            float v = acc + bias[o];
            if (doclip) v = fminf(fmaxf(v, -20.f), 2.f);
            out[(size_t)b * NACT + o] = v;
        }
    }
}

// ---------------------------------------------------------------------------
extern "C" void kernel_launch(void* const* d_in, const int* in_sizes, int n_in,
                              void* d_out, int out_size)
{
    const float* state = (const float*)d_in[0];
    const float* w1  = (const float*)d_in[1];  const float* b1  = (const float*)d_in[2];
    const float* w2  = (const float*)d_in[3];  const float* b2  = (const float*)d_in[4];
    const float* w3  = (const float*)d_in[5];  const float* b3  = (const float*)d_in[6];
    const float* wl  = (const float*)d_in[7];  const float* bl  = (const float*)d_in[8];
    const float* w11 = (const float*)d_in[9];  const float* b11 = (const float*)d_in[10];
    const float* w12 = (const float*)d_in[11]; const float* b12 = (const float*)d_in[12];
    const float* w21 = (const float*)d_in[13]; const float* b21 = (const float*)d_in[14];
    const float* w22 = (const float*)d_in[15]; const float* b22 = (const float*)d_in[16];
    const float* wm  = (const float*)d_in[17]; const float* bm  = (const float*)d_in[18];
    const float* ws  = (const float*)d_in[19]; const float* bs  = (const float*)d_in[20];
    float* out = (float*)d_out;

    float *pI, *pAc, *pW123c, *pB123, *pXc, *pWh1c, *pBh1;
    float *pH1m, *pH1s, *pW12c, *pW22c, *pH2, *pIrep;
    int *pFlag, *pCnt;
    cudaGetSymbolAddress((void**)&pI,     g_I);
    cudaGetSymbolAddress((void**)&pAc,    g_Ac);
    cudaGetSymbolAddress((void**)&pW123c, g_W123c);
    cudaGetSymbolAddress((void**)&pB123,  g_b123);
    cudaGetSymbolAddress((void**)&pXc,    g_Xc);
    cudaGetSymbolAddress((void**)&pWh1c,  g_Wh1c);
    cudaGetSymbolAddress((void**)&pBh1,   g_bh1);
    cudaGetSymbolAddress((void**)&pH1m,   g_H1m);
    cudaGetSymbolAddress((void**)&pH1s,   g_H1s);
    cudaGetSymbolAddress((void**)&pW12c,  g_W12c);
    cudaGetSymbolAddress((void**)&pW22c,  g_W22c);
    cudaGetSymbolAddress((void**)&pH2,    g_H2);
    cudaGetSymbolAddress((void**)&pFlag,  g_flag);
    cudaGetSymbolAddress((void**)&pCnt,   g_cnt);
    cudaGetSymbolAddress((void**)&pIrep,  g_Irep);

    cudaFuncSetAttribute(gemm_tf32<0>, cudaFuncAttributeMaxDynamicSharedMemorySize, SMEM_GEMM);
    cudaFuncSetAttribute(gemm_tf32<1>, cudaFuncAttributeMaxDynamicSharedMemorySize, SMEM_GEMM);
    cudaFuncSetAttribute(gemm_tf32<2>, cudaFuncAttributeMaxDynamicSharedMemorySize, SMEM_GEMM);

    const dim3 blk(256);

    cudaMemsetAsync(pCnt, 0, sizeof(int));

    // ---- operand prep ----
    {
        int n = BATCH * FRAMES * NIN;   // state -> [t0, t1, t0]
        split_tf32_A<<<(n + 255) / 256, blk>>>(state, pAc, NIN, n);
        n = HID * NIN;                  // w1|w2|w3 stacked along N -> [w0, w0, w1]
        split_tf32_B<<<(n + 255) / 256, blk>>>(w1, pW123c + (size_t)0 * HID * 3 * NIN, NIN, n);
        split_tf32_B<<<(n + 255) / 256, blk>>>(w2, pW123c + (size_t)1 * HID * 3 * NIN, NIN, n);
        split_tf32_B<<<(n + 255) / 256, blk>>>(w3, pW123c + (size_t)2 * HID * 3 * NIN, NIN, n);
        n = HID * 4 * HID;              // (w11|w21)/15 -> [w0, w1]
        split_tf32_B2_scaled<<<(n + 255) / 256, blk>>>(w11, pWh1c, 1.f / 15.f, 4 * HID, n);
        split_tf32_B2_scaled<<<(n + 255) / 256, blk>>>(w21, pWh1c + (size_t)HID * 2 * 4 * HID,
                                                       1.f / 15.f, 4 * HID, n);
        n = HID * HID;                  // w12 / w22 -> [w0, w0, w1]
        split_tf32_B<<<(n + 255) / 256, blk>>>(w12, pW12c, HID, n);
        split_tf32_B<<<(n + 255) / 256, blk>>>(w22, pW22c, HID, n);

        cudaMemcpyAsync(pB123,           b1,  HID * 4, cudaMemcpyDeviceToDevice);
        cudaMemcpyAsync(pB123 + HID,     b2,  HID * 4, cudaMemcpyDeviceToDevice);
        cudaMemcpyAsync(pB123 + 2 * HID, b3,  HID * 4, cudaMemcpyDeviceToDevice);
        cudaMemcpyAsync(pBh1,            b11, HID * 4, cudaMemcpyDeviceToDevice);
        cudaMemcpyAsync(pBh1 + HID,      b21, HID * 4, cudaMemcpyDeviceToDevice);
    }

    // ---- phase 1: stacked tf32 3-product GEMM (K'=1536) -> g_I[b,f,j,h] ----
    {
        const dim3 g(3 * HID / 128, BATCH * FRAMES / 128);   // (24, 80)
        gemm_tf32<0><<<g, blk, SMEM_GEMM>>>(BATCH * FRAMES, 3 * HID, 3 * NIN,
            pAc, pW123c, pB123, pI, 3 * HID, nullptr, nullptr);
    }

    // ---- phase 2: LIF scan with near-threshold flagging ----
    scan_flag_kernel<<<(BATCH * HID) / 256, blk>>>(pI, wl, bl, pXc, pFlag, pCnt);
    repair_dots_kernel<<<(MAXFLAG * 15 + 255) / 256, blk>>>(
        state, w1, b1, w2, b2, w3, b3, pFlag, pCnt, pIrep);
    repair_scan_kernel<<<(MAXFLAG + 255) / 256, blk>>>(pIrep, wl, bl, pFlag, pCnt, pXc);

    // ---- phase 3: heads on tf32 tensor pipe (unchanged from R9) ----
    {
        const dim3 g(2 * HID / 128, BATCH / 128);
        gemm_tf32<2><<<g, blk, SMEM_GEMM>>>(BATCH, 2 * HID, 2 * 4 * HID,
            pXc, pWh1c, pBh1, nullptr, 0, pH1m, pH1s);
    }
    {
        const dim3 g(HID / 128, BATCH / 128);
        gemm_tf32<1><<<g, blk, SMEM_GEMM>>>(BATCH, HID, 3 * HID,
            pH1m, pW12c, b12, pH2, HID, nullptr, nullptr);
        head_out_kernel<<<BATCH, blk>>>(pH2, wm, bm, out, 0);
        gemm_tf32<1><<<g, blk, SMEM_GEMM>>>(BATCH, HID, 3 * HID,
            pH1s, pW22c, b22, pH2, HID, nullptr, nullptr);
        head_out_kernel<<<BATCH, blk>>>(pH2, ws, bs, out + (size_t)BATCH * NACT, 1);
    }
}

// round 13
// speedup vs baseline: 2.8166x; 1.6942x over previous
#include <cuda_runtime.h>
#include <cuda_fp16.h>
#include <cstdint>

// ---------------------------------------------------------------------------
// GaussianPolicy forward — fp16 HMMA everywhere + flag-and-repair.
//   B=2048, NIN=512, HID=1024, NACT=32, 5 frames repeated 3x -> 15 LIF steps.
// Correctness anchor: spike counts are made BITWISE identical to the passing
//   R9/R12 runs. Phase-1 runs as fp16 3-product GEMM (deviation ~5e-7);
//   any lane whose LIF membrane comes within EPS=3e-5 of threshold is
//   recomputed with serial fmaf (bit-identical to R9's sgemm) and re-scanned.
// Heads (1e-3 tolerance, pure rounding): fp16 split GEMMs, err ~2^-22.
//   L1: A=[count, count/256] (exact), B=[w0, 256*w1] of w/15, K'=8192
//   L2: A=[h, h/64, 64e], B=[w0, 64w1, w0/64], K'=3072
// ---------------------------------------------------------------------------

namespace {
constexpr int BATCH = 2048, NIN = 512, HID = 1024, NACT = 32, FRAMES = 5;
constexpr int ROWB   = 112;              // 64B fp16 data (32 elems) + 48B pad
constexpr int TILEB  = 128 * ROWB;       // 14336 B per operand tile
constexpr int STAGEB = 2 * TILEB;
constexpr int NSTAGE = 3;
constexpr int SMEM_GEMM = NSTAGE * STAGEB;  // 86016 B
constexpr int MAXFLAG = 262144;
constexpr float EPS = 3e-5f;
}

// ------------------------------ scratch (alloc-free rule) -------------------
__device__ __align__(256) float  g_I    [(size_t)BATCH * FRAMES * 3 * HID]; // [b,f,j,h]
__device__ __align__(256) __half g_Ac   [(size_t)BATCH * FRAMES * 3 * NIN]; // state A-split3
__device__ __align__(256) __half g_W123c[(size_t)3 * HID * 3 * NIN];        // w1|w2|w3 B-split3
__device__ __align__(256) float  g_b123 [3 * HID];
__device__ __align__(256) __half g_Xc   [(size_t)BATCH * 2 * 4 * HID];      // [count, count/256]
__device__ __align__(256) __half g_Wh1c [(size_t)2 * HID * 2 * 4 * HID];    // (w11|w21)/15 2-seg
__device__ __align__(256) float  g_bh1  [2 * HID];
__device__ __align__(256) __half g_H1m  [(size_t)BATCH * 3 * HID];          // A-split3
__device__ __align__(256) __half g_H1s  [(size_t)BATCH * 3 * HID];
__device__ __align__(256) __half g_W12c [(size_t)HID * 3 * HID];            // B-split3
__device__ __align__(256) __half g_W22c [(size_t)HID * 3 * HID];
__device__ __align__(256) float  g_H2   [(size_t)BATCH * HID];
__device__ __align__(256) int    g_flag [MAXFLAG];
__device__               int     g_cnt;
__device__ __align__(256) float  g_Irep [(size_t)MAXFLAG * 15];

// ------------------------------ PTX helpers ---------------------------------
__device__ __forceinline__ uint32_t smem_u32(const void* p) {
    uint32_t a;
    asm("{ .reg .u64 t; cvta.to.shared.u64 t, %1; cvt.u32.u64 %0, t; }" : "=r"(a) : "l"(p));
    return a;
}
__device__ __forceinline__ void cpasync16(uint32_t dst, const void* src) {
    asm volatile("cp.async.cg.shared.global [%0], [%1], 16;" :: "r"(dst), "l"(src));
}
__device__ __forceinline__ void cp_commit() {
    asm volatile("cp.async.commit_group;" ::: "memory");
}
template<int N> __device__ __forceinline__ void cp_wait() {
    asm volatile("cp.async.wait_group %0;" :: "n"(N) : "memory");
}
__device__ __forceinline__ void ldsm4(uint32_t* r, uint32_t addr) {
    asm volatile("ldmatrix.sync.aligned.m8n8.x4.shared.b16 {%0,%1,%2,%3}, [%4];"
                 : "=r"(r[0]), "=r"(r[1]), "=r"(r[2]), "=r"(r[3]) : "r"(addr));
}
__device__ __forceinline__ void mma16816(float* d, const uint32_t* a, uint32_t b0, uint32_t b1) {
    asm volatile(
        "mma.sync.aligned.m16n8k16.row.col.f32.f16.f16.f32 "
        "{%0,%1,%2,%3}, {%4,%5,%6,%7}, {%8,%9}, {%0,%1,%2,%3};"
        : "+f"(d[0]), "+f"(d[1]), "+f"(d[2]), "+f"(d[3])
        : "r"(a[0]), "r"(a[1]), "r"(a[2]), "r"(a[3]), "r"(b0), "r"(b1));
}
// fp16 2-split, scaled segments (A pattern: [h, h/64, 64e]; B: [h, 64e, h/64])
__device__ __forceinline__ void fp16_split(float v, __half& h, __half& hd, __half& eu) {
    h = __float2half_rn(v);
    float e = v - __half2float(h);
    hd = __float2half_rn(__half2float(h) * (1.f / 64.f));
    eu = __float2half_rn(e * 64.f);
}

// ---------------------------------------------------------------------------
// NT fp16 GEMM: C[M,N] = A[M,K]*B[N,K]^T (+bias, epilogues).
// EPI 0: bias fp32.  EPI 1: relu fp32.
// EPI 2: relu -> A-pattern split3 into O0 (col<HID) / O1 (col>=HID),
//        row stride 3*HID = [h | h/64 | 64e].
// 128x128x32 tile, 8 warps (2x4), warp tile 64x32, 3-stage cp.async pipeline.
// ---------------------------------------------------------------------------
template<int EPI>
__global__ void __launch_bounds__(256, 2) gemm_mma(
    int M, int N, int K,
    const __half* __restrict__ A, const __half* __restrict__ B,
    const float* __restrict__ bias,
    float* __restrict__ C, int ldc,
    __half* __restrict__ O0, __half* __restrict__ O1)
{
    extern __shared__ char smem[];
    const uint32_t sbase = smem_u32(smem);
    const int tid = threadIdx.x;
    const int lane = tid & 31, w = tid >> 5;
    const int wm = w >> 2, wn = w & 3;
    const int bm = blockIdx.y * 128, bn = blockIdx.x * 128;

    float acc[4][4][4];
    #pragma unroll
    for (int i = 0; i < 4; i++)
        #pragma unroll
        for (int j = 0; j < 4; j++)
            #pragma unroll
            for (int k = 0; k < 4; k++) acc[i][j][k] = 0.f;

    const int nch = K >> 5;

    auto issue_loads = [&](int s, int c) {
        const int kc = c << 5;
        const uint32_t base = sbase + s * STAGEB;
        #pragma unroll
        for (int t = 0; t < 4; t++) {
            const int idx = t * 256 + tid;
            const int isB = idx >> 9;
            const int r   = (idx >> 2) & 127;
            const int g   = idx & 3;
            const __half* src = (isB ? B + (size_t)(bn + r) * K
                                     : A + (size_t)(bm + r) * K) + kc + g * 8;
            cpasync16(base + isB * TILEB + (uint32_t)(r * ROWB + g * 16), src);
        }
    };
    auto compute_stage = [&](int s) {
        const uint32_t sa = sbase + s * STAGEB + (uint32_t)(wm * 64) * ROWB;
        const uint32_t sb = sbase + s * STAGEB + TILEB + (uint32_t)(wn * 32) * ROWB;
        const int lr = lane & 15, lg = lane >> 4;
        #pragma unroll
        for (int ks = 0; ks < 2; ks++) {
            uint32_t a[4][4], b[2][4];
            #pragma unroll
            for (int ma = 0; ma < 4; ma++)
                ldsm4(a[ma], sa + (uint32_t)((ma * 16 + lr) * ROWB + (ks * 2 + lg) * 16));
            #pragma unroll
            for (int nb = 0; nb < 2; nb++)
                ldsm4(b[nb], sb + (uint32_t)((nb * 16 + lr) * ROWB + (ks * 2 + lg) * 16));
            #pragma unroll
            for (int ma = 0; ma < 4; ma++)
                #pragma unroll
                for (int na = 0; na < 4; na++)
                    mma16816(acc[ma][na], a[ma], b[na >> 1][na & 1], b[na >> 1][(na & 1) + 2]);
        }
    };

    #pragma unroll
    for (int c = 0; c < NSTAGE; c++) {
        if (c < nch) issue_loads(c, c);
        cp_commit();
    }
    for (int c = 0; c < nch; c++) {
        const int s = c % NSTAGE;
        cp_wait<NSTAGE - 1>();
        __syncthreads();
        compute_stage(s);
        __syncthreads();
        if (c + NSTAGE < nch) issue_loads(s, c + NSTAGE);
        cp_commit();
    }

    const int r0b  = bm + wm * 64 + (lane >> 2);
    const int colb = bn + wn * 32 + (lane & 3) * 2;
    #pragma unroll
    for (int ma = 0; ma < 4; ma++) {
        const int r0 = r0b + ma * 16;
        #pragma unroll
        for (int na = 0; na < 4; na++) {
            const int col = colb + na * 8;
            const float bv0 = bias[col], bv1 = bias[col + 1];
            float v00 = acc[ma][na][0] + bv0, v01 = acc[ma][na][1] + bv1;
            float v10 = acc[ma][na][2] + bv0, v11 = acc[ma][na][3] + bv1;
            if (EPI >= 1) {
                v00 = fmaxf(v00, 0.f); v01 = fmaxf(v01, 0.f);
                v10 = fmaxf(v10, 0.f); v11 = fmaxf(v11, 0.f);
            }
            if (EPI <= 1) {
                *(float2*)&C[(size_t)r0 * ldc + col]       = make_float2(v00, v01);
                *(float2*)&C[(size_t)(r0 + 8) * ldc + col] = make_float2(v10, v11);
            } else {
                __half* buf = (col < HID) ? O0 : O1;
                const int cc = col & (HID - 1);
                #pragma unroll
                for (int hr = 0; hr < 2; hr++) {
                    const int rr = r0 + hr * 8;
                    const float u0 = hr ? v10 : v00;
                    const float u1 = hr ? v11 : v01;
                    __half h0, h0d, e0u, h1, h1d, e1u;
                    fp16_split(u0, h0, h0d, e0u);
                    fp16_split(u1, h1, h1d, e1u);
                    __half* p = buf + (size_t)rr * (3 * HID) + cc;
                    *(__half2*)(p)           = __halves2half2(h0, h1);
                    *(__half2*)(p + HID)     = __halves2half2(h0d, h1d);
                    *(__half2*)(p + 2 * HID) = __halves2half2(e0u, e1u);
                }
            }
        }
    }
}

// ------------------------------ split kernels -------------------------------
// A pattern: [h, h/64, 64e]
__global__ void __launch_bounds__(256) split_concat_A(
    const float* __restrict__ in, __half* __restrict__ out, int K, int n)
{
    int i = blockIdx.x * 256 + threadIdx.x;
    if (i >= n) return;
    int r = i / K, k = i - r * K;
    __half h, hd, eu;
    fp16_split(in[i], h, hd, eu);
    __half* p = out + (size_t)r * 3 * K + k;
    p[0] = h; p[K] = hd; p[2 * K] = eu;
}
// B pattern: [h, 64e, h/64]
__global__ void __launch_bounds__(256) split_concat_B(
    const float* __restrict__ in, __half* __restrict__ out, int K, int n)
{
    int i = blockIdx.x * 256 + threadIdx.x;
    if (i >= n) return;
    int r = i / K, k = i - r * K;
    __half h, hd, eu;
    fp16_split(in[i], h, hd, eu);
    __half* p = out + (size_t)r * 3 * K + k;
    p[0] = h; p[K] = eu; p[2 * K] = hd;
}
// Head-L1 weights: w*scale -> [w0, 256*resid]
__global__ void __launch_bounds__(256) split2B_scaled(
    const float* __restrict__ in, __half* __restrict__ out, float scale, int K, int n)
{
    int i = blockIdx.x * 256 + threadIdx.x;
    if (i >= n) return;
    int r = i / K, k = i - r * K;
    float v = in[i] * scale;
    __half h0 = __float2half_rn(v);
    float e = v - __half2float(h0);
    __half* p = out + (size_t)r * 2 * K + k;
    p[0] = h0;
    p[K] = __float2half_rn(e * 256.f);
}

// ------------------------------ LIF scan + flag ------------------------------
__global__ void __launch_bounds__(256) scan_flag_kernel(
    const float* __restrict__ I,   // [b, f, j, h]  (fp16-GEMM result)
    const float* __restrict__ wl, const float* __restrict__ bl,
    __half* __restrict__ Xc, int* __restrict__ flags, int* __restrict__ cnt)
{
    const int idx = blockIdx.x * 256 + threadIdx.x;
    const int b = idx >> 10;
    const int h = idx & (HID - 1);
    if (b >= BATCH) return;

    const float wl0 = wl[0], wl1 = wl[1], wl2 = wl[2], blv = bl[0];
    float m0 = 0.f, m1 = 0.f, m2 = 0.f, m3 = 0.f;
    float s0 = 0.f, s1 = 0.f, s2 = 0.f, s3 = 0.f;
    float a0 = 0.f, a1 = 0.f, a2 = 0.f, a3 = 0.f;
    float gap = 1e30f;

    const float* Ib = I + (size_t)b * FRAMES * 3 * HID + h;
    #pragma unroll
    for (int f = 0; f < FRAMES; f++) {
        const float i1 = Ib[(f * 3 + 0) * HID];
        const float i2 = Ib[(f * 3 + 1) * HID];
        const float i3 = Ib[(f * 3 + 2) * HID];
        #pragma unroll
        for (int r = 0; r < 3; r++) {
            const float inner = fmaf(m0, wl0, fmaf(m1, wl1, fmaf(m2, wl2, blv)));
            m0 = (m0 * 0.2f) * (1.f - s0) + i1;
            m1 = (m1 * 0.2f) * (1.f - s1) + i2;
            m2 = (m2 * 0.2f) * (1.f - s2) + i3;
            m3 = (m3 * 0.2f) * (1.f - s3) + inner;
            gap = fminf(gap, fabsf(m0 - 0.8f));
            gap = fminf(gap, fabsf(m1 - 0.8f));
            gap = fminf(gap, fabsf(m2 - 0.8f));
            gap = fminf(gap, fabsf(m3 - 0.8f));
            s0 = (m0 > 0.8f) ? 1.f : 0.f;
            s1 = (m1 > 0.8f) ? 1.f : 0.f;
            s2 = (m2 > 0.8f) ? 1.f : 0.f;
            s3 = (m3 > 0.8f) ? 1.f : 0.f;
            a0 += s0; a1 += s1; a2 += s2; a3 += s3;
        }
    }
    if (gap < EPS) {
        int slot = atomicAdd(cnt, 1);
        if (slot < MAXFLAG) flags[slot] = idx;
    }
    // counts exact in fp16; count/256 exact (power-of-2 scale)
    __half c0[4], c1[4];
    const float cv[4] = {a0, a1, a2, a3};
    #pragma unroll
    for (int k = 0; k < 4; k++) {
        c0[k] = __float2half_rn(cv[k]);
        c1[k] = __float2half_rn(cv[k] * (1.f / 256.f));
    }
    uint2 u0, u1;
    __half2 t;
    t = __halves2half2(c0[0], c0[1]); u0.x = *(uint32_t*)&t;
    t = __halves2half2(c0[2], c0[3]); u0.y = *(uint32_t*)&t;
    t = __halves2half2(c1[0], c1[1]); u1.x = *(uint32_t*)&t;
    t = __halves2half2(c1[2], c1[3]); u1.y = *(uint32_t*)&t;
    const size_t ob = (size_t)b * (2 * 4 * HID) + h * 4;
    *(uint2*)(Xc + ob)           = u0;
    *(uint2*)(Xc + ob + 4 * HID) = u1;
}

// ------------------------------ repair --------------------------------------
__global__ void __launch_bounds__(256) repair_dots_kernel(
    const float* __restrict__ state,
    const float* __restrict__ w1, const float* __restrict__ b1,
    const float* __restrict__ w2, const float* __restrict__ b2,
    const float* __restrict__ w3, const float* __restrict__ b3,
    const int* __restrict__ flags, const int* __restrict__ cnt,
    float* __restrict__ Irep)
{
    const int idx = blockIdx.x * 256 + threadIdx.x;
    const int lane_i = idx / 15;
    const int t = idx - lane_i * 15;
    const int n = min(*cnt, MAXFLAG);
    if (lane_i >= n) return;
    const int bh = flags[lane_i];
    const int b = bh >> 10, h = bh & (HID - 1);
    const int f = t / 3, j = t - f * 3;

    const float* a = state + ((size_t)b * FRAMES + f) * NIN;
    const float* wv = (j == 0 ? w1 : (j == 1 ? w2 : w3)) + (size_t)h * NIN;
    const float* bv = (j == 0 ? b1 : (j == 1 ? b2 : b3));
    float acc = 0.f;
    for (int k = 0; k < NIN; k++)
        acc = fmaf(a[k], wv[k], acc);
    Irep[(size_t)lane_i * 15 + t] = acc + bv[h];
}

__global__ void __launch_bounds__(256) repair_scan_kernel(
    const float* __restrict__ Irep,
    const float* __restrict__ wl, const float* __restrict__ bl,
    const int* __restrict__ flags, const int* __restrict__ cnt,
    __half* __restrict__ Xc)
{
    const int lane_i = blockIdx.x * 256 + threadIdx.x;
    const int n = min(*cnt, MAXFLAG);
    if (lane_i >= n) return;
    const int bh = flags[lane_i];
    const int b = bh >> 10, h = bh & (HID - 1);

    const float wl0 = wl[0], wl1 = wl[1], wl2 = wl[2], blv = bl[0];
    float m0 = 0.f, m1 = 0.f, m2 = 0.f, m3 = 0.f;
    float s0 = 0.f, s1 = 0.f, s2 = 0.f, s3 = 0.f;
    float a0 = 0.f, a1 = 0.f, a2 = 0.f, a3 = 0.f;

    const float* Ib = Irep + (size_t)lane_i * 15;
    #pragma unroll
    for (int f = 0; f < FRAMES; f++) {
        const float i1 = Ib[f * 3 + 0];
        const float i2 = Ib[f * 3 + 1];
        const float i3 = Ib[f * 3 + 2];
        #pragma unroll
        for (int r = 0; r < 3; r++) {
            const float inner = fmaf(m0, wl0, fmaf(m1, wl1, fmaf(m2, wl2, blv)));
            m0 = (m0 * 0.2f) * (1.f - s0) + i1;
            m1 = (m1 * 0.2f) * (1.f - s1) + i2;
            m2 = (m2 * 0.2f) * (1.f - s2) + i3;
            m3 = (m3 * 0.2f) * (1.f - s3) + inner;
            s0 = (m0 > 0.8f) ? 1.f : 0.f;
            s1 = (m1 > 0.8f) ? 1.f : 0.f;
            s2 = (m2 > 0.8f) ? 1.f : 0.f;
            s3 = (m3 > 0.8f) ? 1.f : 0.f;
            a0 += s0; a1 += s1; a2 += s2; a3 += s3;
        }
    }
    __half c0[4], c1[4];
    const float cv[4] = {a0, a1, a2, a3};
    #pragma unroll
    for (int k = 0; k < 4; k++) {
        c0[k] = __float2half_rn(cv[k]);
        c1[k] = __float2half_rn(cv[k] * (1.f / 256.f));
    }
    uint2 u0, u1;
    __half2 t;
    t = __halves2half2(c0[0], c0[1]); u0.x = *(uint32_t*)&t;
    t = __halves2half2(c0[2], c0[3]); u0.y = *(uint32_t*)&t;
    t = __halves2half2(c1[0], c1[1]); u1.x = *(uint32_t*)&t;
    t = __halves2half2(c1[2], c1[3]); u1.y = *(uint32_t*)&t;
    const size_t ob = (size_t)b * (2 * 4 * HID) + h * 4;
    *(uint2*)(Xc + ob)           = u0;
    *(uint2*)(Xc + ob + 4 * HID) = u1;
}

// ------------------------------ tiny output layer ---------------------------
__global__ void __launch_bounds__(256) head_out_kernel(
    const float* __restrict__ X, const float* __restrict__ W,
    const float* __restrict__ bias, float* __restrict__ out, int doclip)
{
    __shared__ float xs[HID];
    const int b = blockIdx.x;
    const float* xrow = X + (size_t)b * HID;
    for (int i = threadIdx.x; i < HID; i += 256) xs[i] = xrow[i];
    __syncthreads();

    const int warp = threadIdx.x >> 5;
    const int lane = threadIdx.x & 31;
    for (int o = warp; o < NACT; o += 8) {
        const float* wrow = W + (size_t)o * HID;
        float acc = 0.f;
        #pragma unroll 4
        for (int k = lane; k < HID; k += 32)
            acc = fmaf(xs[k], wrow[k], acc);
        #pragma unroll
        for (int s = 16; s > 0; s >>= 1)
            acc += __shfl_xor_sync(0xffffffff, acc, s);
        if (lane == 0) {
            float v = acc + bias[o];
            if (doclip) v = fminf(fmaxf(v, -20.f), 2.f);
            out[(size_t)b * NACT + o] = v;
        }
    }
}

// ---------------------------------------------------------------------------
extern "C" void kernel_launch(void* const* d_in, const int* in_sizes, int n_in,
                              void* d_out, int out_size)
{
    const float* state = (const float*)d_in[0];
    const float* w1  = (const float*)d_in[1];  const float* b1  = (const float*)d_in[2];
    const float* w2  = (const float*)d_in[3];  const float* b2  = (const float*)d_in[4];
    const float* w3  = (const float*)d_in[5];  const float* b3  = (const float*)d_in[6];
    const float* wl  = (const float*)d_in[7];  const float* bl  = (const float*)d_in[8];
    const float* w11 = (const float*)d_in[9];  const float* b11 = (const float*)d_in[10];
    const float* w12 = (const float*)d_in[11]; const float* b12 = (const float*)d_in[12];
    const float* w21 = (const float*)d_in[13]; const float* b21 = (const float*)d_in[14];
    const float* w22 = (const float*)d_in[15]; const float* b22 = (const float*)d_in[16];
    const float* wm  = (const float*)d_in[17]; const float* bm  = (const float*)d_in[18];
    const float* ws  = (const float*)d_in[19]; const float* bs  = (const float*)d_in[20];
    float* out = (float*)d_out;

    float *pI, *pB123, *pBh1, *pH2, *pIrep;
    __half *pAc, *pW123c, *pXc, *pWh1c, *pH1m, *pH1s, *pW12c, *pW22c;
    int *pFlag, *pCnt;
    cudaGetSymbolAddress((void**)&pI,     g_I);
    cudaGetSymbolAddress((void**)&pAc,    g_Ac);
    cudaGetSymbolAddress((void**)&pW123c, g_W123c);
    cudaGetSymbolAddress((void**)&pB123,  g_b123);
    cudaGetSymbolAddress((void**)&pXc,    g_Xc);
    cudaGetSymbolAddress((void**)&pWh1c,  g_Wh1c);
    cudaGetSymbolAddress((void**)&pBh1,   g_bh1);
    cudaGetSymbolAddress((void**)&pH1m,   g_H1m);
    cudaGetSymbolAddress((void**)&pH1s,   g_H1s);
    cudaGetSymbolAddress((void**)&pW12c,  g_W12c);
    cudaGetSymbolAddress((void**)&pW22c,  g_W22c);
    cudaGetSymbolAddress((void**)&pH2,    g_H2);
    cudaGetSymbolAddress((void**)&pFlag,  g_flag);
    cudaGetSymbolAddress((void**)&pCnt,   g_cnt);
    cudaGetSymbolAddress((void**)&pIrep,  g_Irep);

    cudaFuncSetAttribute(gemm_mma<0>, cudaFuncAttributeMaxDynamicSharedMemorySize, SMEM_GEMM);
    cudaFuncSetAttribute(gemm_mma<1>, cudaFuncAttributeMaxDynamicSharedMemorySize, SMEM_GEMM);
    cudaFuncSetAttribute(gemm_mma<2>, cudaFuncAttributeMaxDynamicSharedMemorySize, SMEM_GEMM);

    const dim3 blk(256);

    cudaMemsetAsync(pCnt, 0, sizeof(int));

    // ---- operand prep ----
    {
        int n = BATCH * FRAMES * NIN;   // state -> A-split3
        split_concat_A<<<(n + 255) / 256, blk>>>(state, pAc, NIN, n);
        n = HID * NIN;                  // w1|w2|w3 stacked along N -> B-split3
        split_concat_B<<<(n + 255) / 256, blk>>>(w1, pW123c + (size_t)0 * HID * 3 * NIN, NIN, n);
        split_concat_B<<<(n + 255) / 256, blk>>>(w2, pW123c + (size_t)1 * HID * 3 * NIN, NIN, n);
        split_concat_B<<<(n + 255) / 256, blk>>>(w3, pW123c + (size_t)2 * HID * 3 * NIN, NIN, n);
        n = HID * 4 * HID;              // (w11|w21)/15 -> [w0, 256w1]
        split2B_scaled<<<(n + 255) / 256, blk>>>(w11, pWh1c, 1.f / 15.f, 4 * HID, n);
        split2B_scaled<<<(n + 255) / 256, blk>>>(w21, pWh1c + (size_t)HID * 2 * 4 * HID,
                                                 1.f / 15.f, 4 * HID, n);
        n = HID * HID;                  // w12 / w22 -> B-split3
        split_concat_B<<<(n + 255) / 256, blk>>>(w12, pW12c, HID, n);
        split_concat_B<<<(n + 255) / 256, blk>>>(w22, pW22c, HID, n);

        cudaMemcpyAsync(pB123,           b1,  HID * 4, cudaMemcpyDeviceToDevice);
        cudaMemcpyAsync(pB123 + HID,     b2,  HID * 4, cudaMemcpyDeviceToDevice);
        cudaMemcpyAsync(pB123 + 2 * HID, b3,  HID * 4, cudaMemcpyDeviceToDevice);
        cudaMemcpyAsync(pBh1,            b11, HID * 4, cudaMemcpyDeviceToDevice);
        cudaMemcpyAsync(pBh1 + HID,      b21, HID * 4, cudaMemcpyDeviceToDevice);
    }

    // ---- phase 1: stacked fp16 3-product GEMM (K'=1536) -> g_I[b,f,j,h] ----
    {
        const dim3 g(3 * HID / 128, BATCH * FRAMES / 128);   // (24, 80)
        gemm_mma<0><<<g, blk, SMEM_GEMM>>>(BATCH * FRAMES, 3 * HID, 3 * NIN,
            pAc, pW123c, pB123, pI, 3 * HID, nullptr, nullptr);
    }

    // ---- phase 2: LIF scan + flag, then repair flagged lanes exactly ----
    scan_flag_kernel<<<(BATCH * HID) / 256, blk>>>(pI, wl, bl, pXc, pFlag, pCnt);
    repair_dots_kernel<<<(MAXFLAG * 15 + 255) / 256, blk>>>(
        state, w1, b1, w2, b2, w3, b3, pFlag, pCnt, pIrep);
    repair_scan_kernel<<<(MAXFLAG + 255) / 256, blk>>>(pIrep, wl, bl, pFlag, pCnt, pXc);

    // ---- phase 3: heads on fp16 HMMA ----
    {   // layer 1, both heads stacked along N (K'=8192)
        const dim3 g(2 * HID / 128, BATCH / 128);
        gemm_mma<2><<<g, blk, SMEM_GEMM>>>(BATCH, 2 * HID, 2 * 4 * HID,
            pXc, pWh1c, pBh1, nullptr, 0, pH1m, pH1s);
    }
    {   // layer 2 + output (K'=3072)
        const dim3 g(HID / 128, BATCH / 128);
        gemm_mma<1><<<g, blk, SMEM_GEMM>>>(BATCH, HID, 3 * HID,
            pH1m, pW12c, b12, pH2, HID, nullptr, nullptr);
        head_out_kernel<<<BATCH, blk>>>(pH2, wm, bm, out, 0);
        gemm_mma<1><<<g, blk, SMEM_GEMM>>>(BATCH, HID, 3 * HID,
            pH1s, pW22c, b22, pH2, HID, nullptr, nullptr);
        head_out_kernel<<<BATCH, blk>>>(pH2, ws, bs, out + (size_t)BATCH * NACT, 1);
    }
}

// round 14
// speedup vs baseline: 2.9606x; 1.0511x over previous
#include <cuda_runtime.h>
#include <cuda_fp16.h>
#include <cstdint>

// ---------------------------------------------------------------------------
// GaussianPolicy forward — fp16 HMMA everywhere + flag-and-repair. v2 engine:
// single-barrier multistage pipeline (wait -> sync -> prefetch c+2 -> compute).
//   B=2048, NIN=512, HID=1024, NACT=32, 5 frames repeated 3x -> 15 LIF steps.
// Correctness anchor: spike counts bitwise identical to the passing R9/R12/R13
//   runs via near-threshold flag (EPS=3e-5) + serial-fmaf repair.
// Heads: fp16 split GEMMs (~2^-22), rel_err 1.36e-5 measured.
// ---------------------------------------------------------------------------

namespace {
constexpr int BATCH = 2048, NIN = 512, HID = 1024, NACT = 32, FRAMES = 5;
constexpr int ROWB   = 112;              // 64B fp16 data (32 elems) + 48B pad
constexpr int TILEB  = 128 * ROWB;       // 14336 B per operand tile
constexpr int STAGEB = 2 * TILEB;
constexpr int NSTAGE = 3;
constexpr int SMEM_GEMM = NSTAGE * STAGEB;  // 86016 B
constexpr int MAXFLAG = 262144;
constexpr float EPS = 3e-5f;
}

// ------------------------------ scratch (alloc-free rule) -------------------
__device__ __align__(256) float  g_I    [(size_t)BATCH * FRAMES * 3 * HID]; // [b,f,j,h]
__device__ __align__(256) __half g_Ac   [(size_t)BATCH * FRAMES * 3 * NIN]; // state A-split3
__device__ __align__(256) __half g_W123c[(size_t)3 * HID * 3 * NIN];        // w1|w2|w3 B-split3
__device__ __align__(256) float  g_b123 [3 * HID];
__device__ __align__(256) __half g_Xc   [(size_t)BATCH * 2 * 4 * HID];      // [count, count/256]
__device__ __align__(256) __half g_Wh1c [(size_t)2 * HID * 2 * 4 * HID];    // (w11|w21)/15 2-seg
__device__ __align__(256) float  g_bh1  [2 * HID];
__device__ __align__(256) __half g_H1m  [(size_t)BATCH * 3 * HID];          // A-split3
__device__ __align__(256) __half g_H1s  [(size_t)BATCH * 3 * HID];
__device__ __align__(256) __half g_W12c [(size_t)HID * 3 * HID];            // B-split3
__device__ __align__(256) __half g_W22c [(size_t)HID * 3 * HID];
__device__ __align__(256) float  g_H2m  [(size_t)BATCH * HID];
__device__ __align__(256) float  g_H2s  [(size_t)BATCH * HID];
__device__ __align__(256) int    g_flag [MAXFLAG];
__device__               int     g_cnt;
__device__ __align__(256) float  g_Irep [(size_t)MAXFLAG * 15];

// ------------------------------ PTX helpers ---------------------------------
__device__ __forceinline__ uint32_t smem_u32(const void* p) {
    uint32_t a;
    asm("{ .reg .u64 t; cvta.to.shared.u64 t, %1; cvt.u32.u64 %0, t; }" : "=r"(a) : "l"(p));
    return a;
}
__device__ __forceinline__ void cpasync16(uint32_t dst, const void* src) {
    asm volatile("cp.async.cg.shared.global [%0], [%1], 16;" :: "r"(dst), "l"(src));
}
__device__ __forceinline__ void cp_commit() {
    asm volatile("cp.async.commit_group;" ::: "memory");
}
template<int N> __device__ __forceinline__ void cp_wait() {
    asm volatile("cp.async.wait_group %0;" :: "n"(N) : "memory");
}
__device__ __forceinline__ void ldsm4(uint32_t* r, uint32_t addr) {
    asm volatile("ldmatrix.sync.aligned.m8n8.x4.shared.b16 {%0,%1,%2,%3}, [%4];"
                 : "=r"(r[0]), "=r"(r[1]), "=r"(r[2]), "=r"(r[3]) : "r"(addr));
}
__device__ __forceinline__ void mma16816(float* d, const uint32_t* a, uint32_t b0, uint32_t b1) {
    asm volatile(
        "mma.sync.aligned.m16n8k16.row.col.f32.f16.f16.f32 "
        "{%0,%1,%2,%3}, {%4,%5,%6,%7}, {%8,%9}, {%0,%1,%2,%3};"
        : "+f"(d[0]), "+f"(d[1]), "+f"(d[2]), "+f"(d[3])
        : "r"(a[0]), "r"(a[1]), "r"(a[2]), "r"(a[3]), "r"(b0), "r"(b1));
}
__device__ __forceinline__ void fp16_split(float v, __half& h, __half& hd, __half& eu) {
    h = __float2half_rn(v);
    float e = v - __half2float(h);
    hd = __float2half_rn(__half2float(h) * (1.f / 64.f));
    eu = __float2half_rn(e * 64.f);
}

// ---------------------------------------------------------------------------
// NT fp16 GEMM: C[M,N] = A[M,K]*B[N,K]^T (+bias, epilogues).
// EPI 0: bias fp32.  EPI 1: relu fp32.  EPI 2: relu -> A-split3 into O0/O1.
// 128x128x32 tile, 8 warps (2x4), 3-stage cp.async, ONE barrier per chunk.
// ---------------------------------------------------------------------------
template<int EPI>
__global__ void __launch_bounds__(256, 2) gemm_mma(
    int M, int N, int K,
    const __half* __restrict__ A, const __half* __restrict__ B,
    const float* __restrict__ bias,
    float* __restrict__ C, int ldc,
    __half* __restrict__ O0, __half* __restrict__ O1)
{
    extern __shared__ char smem[];
    const uint32_t sbase = smem_u32(smem);
    const int tid = threadIdx.x;
    const int lane = tid & 31, w = tid >> 5;
    const int wm = w >> 2, wn = w & 3;
    const int bm = blockIdx.y * 128, bn = blockIdx.x * 128;

    float acc[4][4][4];
    #pragma unroll
    for (int i = 0; i < 4; i++)
        #pragma unroll
        for (int j = 0; j < 4; j++)
            #pragma unroll
            for (int k = 0; k < 4; k++) acc[i][j][k] = 0.f;

    const int nch = K >> 5;

    auto issue_loads = [&](int s, int c) {
        const int kc = c << 5;
        const uint32_t base = sbase + s * STAGEB;
        #pragma unroll
        for (int t = 0; t < 4; t++) {
            const int idx = t * 256 + tid;
            const int isB = idx >> 9;
            const int r   = (idx >> 2) & 127;
            const int g   = idx & 3;
            const __half* src = (isB ? B + (size_t)(bn + r) * K
                                     : A + (size_t)(bm + r) * K) + kc + g * 8;
            cpasync16(base + isB * TILEB + (uint32_t)(r * ROWB + g * 16), src);
        }
    };
    auto compute_stage = [&](int s) {
        const uint32_t sa = sbase + s * STAGEB + (uint32_t)(wm * 64) * ROWB;
        const uint32_t sb = sbase + s * STAGEB + TILEB + (uint32_t)(wn * 32) * ROWB;
        const int lr = lane & 15, lg = lane >> 4;
        #pragma unroll
        for (int ks = 0; ks < 2; ks++) {
            uint32_t a[4][4], b[2][4];
            #pragma unroll
            for (int ma = 0; ma < 4; ma++)
                ldsm4(a[ma], sa + (uint32_t)((ma * 16 + lr) * ROWB + (ks * 2 + lg) * 16));
            #pragma unroll
            for (int nb = 0; nb < 2; nb++)
                ldsm4(b[nb], sb + (uint32_t)((nb * 16 + lr) * ROWB + (ks * 2 + lg) * 16));
            #pragma unroll
            for (int ma = 0; ma < 4; ma++)
                #pragma unroll
                for (int na = 0; na < 4; na++)
                    mma16816(acc[ma][na], a[ma], b[na >> 1][na & 1], b[na >> 1][(na & 1) + 2]);
        }
    };

    // prologue: prefetch chunks 0 and 1 (one commit group each)
    issue_loads(0, 0);
    cp_commit();
    if (nch > 1) issue_loads(1, 1);
    cp_commit();

    // mainloop: wait(c) -> sync -> prefetch(c+2) -> compute(c)
    for (int c = 0; c < nch; c++) {
        cp_wait<1>();              // chunk c resident (c+1 may be in flight)
        __syncthreads();           // all warps see stage, all done with stage (c+2)%3
        if (c + 2 < nch) issue_loads((c + 2) % NSTAGE, c + 2);
        cp_commit();
        compute_stage(c % NSTAGE);
    }

    // epilogue
    const int r0b  = bm + wm * 64 + (lane >> 2);
    const int colb = bn + wn * 32 + (lane & 3) * 2;
    #pragma unroll
    for (int ma = 0; ma < 4; ma++) {
        const int r0 = r0b + ma * 16;
        #pragma unroll
        for (int na = 0; na < 4; na++) {
            const int col = colb + na * 8;
            const float bv0 = bias[col], bv1 = bias[col + 1];
            float v00 = acc[ma][na][0] + bv0, v01 = acc[ma][na][1] + bv1;
            float v10 = acc[ma][na][2] + bv0, v11 = acc[ma][na][3] + bv1;
            if (EPI >= 1) {
                v00 = fmaxf(v00, 0.f); v01 = fmaxf(v01, 0.f);
                v10 = fmaxf(v10, 0.f); v11 = fmaxf(v11, 0.f);
            }
            if (EPI <= 1) {
                *(float2*)&C[(size_t)r0 * ldc + col]       = make_float2(v00, v01);
                *(float2*)&C[(size_t)(r0 + 8) * ldc + col] = make_float2(v10, v11);
            } else {
                __half* buf = (col < HID) ? O0 : O1;
                const int cc = col & (HID - 1);
                #pragma unroll
                for (int hr = 0; hr < 2; hr++) {
                    const int rr = r0 + hr * 8;
                    const float u0 = hr ? v10 : v00;
                    const float u1 = hr ? v11 : v01;
                    __half h0, h0d, e0u, h1, h1d, e1u;
                    fp16_split(u0, h0, h0d, e0u);
                    fp16_split(u1, h1, h1d, e1u);
                    __half* p = buf + (size_t)rr * (3 * HID) + cc;
                    *(__half2*)(p)           = __halves2half2(h0, h1);
                    *(__half2*)(p + HID)     = __halves2half2(h0d, h1d);
                    *(__half2*)(p + 2 * HID) = __halves2half2(e0u, e1u);
                }
            }
        }
    }
}

// ------------------------------ split kernels -------------------------------
__global__ void __launch_bounds__(256) split_concat_A(
    const float* __restrict__ in, __half* __restrict__ out, int K, int n)
{
    int i = blockIdx.x * 256 + threadIdx.x;
    if (i >= n) return;
    int r = i / K, k = i - r * K;
    __half h, hd, eu;
    fp16_split(in[i], h, hd, eu);
    __half* p = out + (size_t)r * 3 * K + k;
    p[0] = h; p[K] = hd; p[2 * K] = eu;
}
__global__ void __launch_bounds__(256) split_concat_B(
    const float* __restrict__ in, __half* __restrict__ out, int K, int n)
{
    int i = blockIdx.x * 256 + threadIdx.x;
    if (i >= n) return;
    int r = i / K, k = i - r * K;
    __half h, hd, eu;
    fp16_split(in[i], h, hd, eu);
    __half* p = out + (size_t)r * 3 * K + k;
    p[0] = h; p[K] = eu; p[2 * K] = hd;
}
__global__ void __launch_bounds__(256) split2B_scaled(
    const float* __restrict__ in, __half* __restrict__ out, float scale, int K, int n)
{
    int i = blockIdx.x * 256 + threadIdx.x;
    if (i >= n) return;
    int r = i / K, k = i - r * K;
    float v = in[i] * scale;
    __half h0 = __float2half_rn(v);
    float e = v - __half2float(h0);
    __half* p = out + (size_t)r * 2 * K + k;
    p[0] = h0;
    p[K] = __float2half_rn(e * 256.f);
}

// ------------------------------ LIF scan + flag ------------------------------
__global__ void __launch_bounds__(256) scan_flag_kernel(
    const float* __restrict__ I,
    const float* __restrict__ wl, const float* __restrict__ bl,
    __half* __restrict__ Xc, int* __restrict__ flags, int* __restrict__ cnt)
{
    const int idx = blockIdx.x * 256 + threadIdx.x;
    const int b = idx >> 10;
    const int h = idx & (HID - 1);
    if (b >= BATCH) return;

    const float wl0 = wl[0], wl1 = wl[1], wl2 = wl[2], blv = bl[0];
    float m0 = 0.f, m1 = 0.f, m2 = 0.f, m3 = 0.f;
    float s0 = 0.f, s1 = 0.f, s2 = 0.f, s3 = 0.f;
    float a0 = 0.f, a1 = 0.f, a2 = 0.f, a3 = 0.f;
    float gap = 1e30f;

    const float* Ib = I + (size_t)b * FRAMES * 3 * HID + h;
    #pragma unroll
    for (int f = 0; f < FRAMES; f++) {
        const float i1 = Ib[(f * 3 + 0) * HID];
        const float i2 = Ib[(f * 3 + 1) * HID];
        const float i3 = Ib[(f * 3 + 2) * HID];
        #pragma unroll
        for (int r = 0; r < 3; r++) {
            const float inner = fmaf(m0, wl0, fmaf(m1, wl1, fmaf(m2, wl2, blv)));
            m0 = (m0 * 0.2f) * (1.f - s0) + i1;
            m1 = (m1 * 0.2f) * (1.f - s1) + i2;
            m2 = (m2 * 0.2f) * (1.f - s2) + i3;
            m3 = (m3 * 0.2f) * (1.f - s3) + inner;
            gap = fminf(gap, fabsf(m0 - 0.8f));
            gap = fminf(gap, fabsf(m1 - 0.8f));
            gap = fminf(gap, fabsf(m2 - 0.8f));
            gap = fminf(gap, fabsf(m3 - 0.8f));
            s0 = (m0 > 0.8f) ? 1.f : 0.f;
            s1 = (m1 > 0.8f) ? 1.f : 0.f;
            s2 = (m2 > 0.8f) ? 1.f : 0.f;
            s3 = (m3 > 0.8f) ? 1.f : 0.f;
            a0 += s0; a1 += s1; a2 += s2; a3 += s3;
        }
    }
    if (gap < EPS) {
        int slot = atomicAdd(cnt, 1);
        if (slot < MAXFLAG) flags[slot] = idx;
    }
    __half c0[4], c1[4];
    const float cv[4] = {a0, a1, a2, a3};
    #pragma unroll
    for (int k = 0; k < 4; k++) {
        c0[k] = __float2half_rn(cv[k]);
        c1[k] = __float2half_rn(cv[k] * (1.f / 256.f));
    }
    uint2 u0, u1;
    __half2 t;
    t = __halves2half2(c0[0], c0[1]); u0.x = *(uint32_t*)&t;
    t = __halves2half2(c0[2], c0[3]); u0.y = *(uint32_t*)&t;
    t = __halves2half2(c1[0], c1[1]); u1.x = *(uint32_t*)&t;
    t = __halves2half2(c1[2], c1[3]); u1.y = *(uint32_t*)&t;
    const size_t ob = (size_t)b * (2 * 4 * HID) + h * 4;
    *(uint2*)(Xc + ob)           = u0;
    *(uint2*)(Xc + ob + 4 * HID) = u1;
}

// ------------------------------ repair --------------------------------------
__global__ void __launch_bounds__(256) repair_dots_kernel(
    const float* __restrict__ state,
    const float* __restrict__ w1, const float* __restrict__ b1,
    const float* __restrict__ w2, const float* __restrict__ b2,
    const float* __restrict__ w3, const float* __restrict__ b3,
    const int* __restrict__ flags, const int* __restrict__ cnt,
    float* __restrict__ Irep)
{
    const int idx = blockIdx.x * 256 + threadIdx.x;
    const int lane_i = idx / 15;
    const int t = idx - lane_i * 15;
    const int n = min(*cnt, MAXFLAG);
    if (lane_i >= n) return;
    const int bh = flags[lane_i];
    const int b = bh >> 10, h = bh & (HID - 1);
    const int f = t / 3, j = t - f * 3;

    const float* a = state + ((size_t)b * FRAMES + f) * NIN;
    const float* wv = (j == 0 ? w1 : (j == 1 ? w2 : w3)) + (size_t)h * NIN;
    const float* bv = (j == 0 ? b1 : (j == 1 ? b2 : b3));
    float acc = 0.f;
    for (int k = 0; k < NIN; k++)
        acc = fmaf(a[k], wv[k], acc);
    Irep[(size_t)lane_i * 15 + t] = acc + bv[h];
}

__global__ void __launch_bounds__(256) repair_scan_kernel(
    const float* __restrict__ Irep,
    const float* __restrict__ wl, const float* __restrict__ bl,
    const int* __restrict__ flags, const int* __restrict__ cnt,
    __half* __restrict__ Xc)
{
    const int lane_i = blockIdx.x * 256 + threadIdx.x;
    const int n = min(*cnt, MAXFLAG);
    if (lane_i >= n) return;
    const int bh = flags[lane_i];
    const int b = bh >> 10, h = bh & (HID - 1);

    const float wl0 = wl[0], wl1 = wl[1], wl2 = wl[2], blv = bl[0];
    float m0 = 0.f, m1 = 0.f, m2 = 0.f, m3 = 0.f;
    float s0 = 0.f, s1 = 0.f, s2 = 0.f, s3 = 0.f;
    float a0 = 0.f, a1 = 0.f, a2 = 0.f, a3 = 0.f;

    const float* Ib = Irep + (size_t)lane_i * 15;
    #pragma unroll
    for (int f = 0; f < FRAMES; f++) {
        const float i1 = Ib[f * 3 + 0];
        const float i2 = Ib[f * 3 + 1];
        const float i3 = Ib[f * 3 + 2];
        #pragma unroll
        for (int r = 0; r < 3; r++) {
            const float inner = fmaf(m0, wl0, fmaf(m1, wl1, fmaf(m2, wl2, blv)));
            m0 = (m0 * 0.2f) * (1.f - s0) + i1;
            m1 = (m1 * 0.2f) * (1.f - s1) + i2;
            m2 = (m2 * 0.2f) * (1.f - s2) + i3;
            m3 = (m3 * 0.2f) * (1.f - s3) + inner;
            s0 = (m0 > 0.8f) ? 1.f : 0.f;
            s1 = (m1 > 0.8f) ? 1.f : 0.f;
            s2 = (m2 > 0.8f) ? 1.f : 0.f;
            s3 = (m3 > 0.8f) ? 1.f : 0.f;
            a0 += s0; a1 += s1; a2 += s2; a3 += s3;
        }
    }
    __half c0[4], c1[4];
    const float cv[4] = {a0, a1, a2, a3};
    #pragma unroll
    for (int k = 0; k < 4; k++) {
        c0[k] = __float2half_rn(cv[k]);
        c1[k] = __float2half_rn(cv[k] * (1.f / 256.f));
    }
    uint2 u0, u1;
    __half2 t;
    t = __halves2half2(c0[0], c0[1]); u0.x = *(uint32_t*)&t;
    t = __halves2half2(c0[2], c0[3]); u0.y = *(uint32_t*)&t;
    t = __halves2half2(c1[0], c1[1]); u1.x = *(uint32_t*)&t;
    t = __halves2half2(c1[2], c1[3]); u1.y = *(uint32_t*)&t;
    const size_t ob = (size_t)b * (2 * 4 * HID) + h * 4;
    *(uint2*)(Xc + ob)           = u0;
    *(uint2*)(Xc + ob + 4 * HID) = u1;
}

// ------------------------------ tiny output layer (both heads) ---------------
__global__ void __launch_bounds__(256) head_out_kernel(
    const float* __restrict__ Xm, const float* __restrict__ Xs,
    const float* __restrict__ Wm, const float* __restrict__ Ws,
    const float* __restrict__ bm, const float* __restrict__ bs,
    float* __restrict__ out)
{
    __shared__ float xs[HID];
    const int b = blockIdx.x;
    const int head = blockIdx.y;              // 0 = mean, 1 = log_std
    const float* X = head ? Xs : Xm;
    const float* W = head ? Ws : Wm;
    const float* bias = head ? bs : bm;
    float* o = out + (size_t)head * BATCH * NACT;

    const float* xrow = X + (size_t)b * HID;
    for (int i = threadIdx.x; i < HID; i += 256) xs[i] = xrow[i];
    __syncthreads();

    const int warp = threadIdx.x >> 5;
    const int lane = threadIdx.x & 31;
    for (int oc = warp; oc < NACT; oc += 8) {
        const float* wrow = W + (size_t)oc * HID;
        float acc = 0.f;
        #pragma unroll 4
        for (int k = lane; k < HID; k += 32)
            acc = fmaf(xs[k], wrow[k], acc);
        #pragma unroll
        for (int s = 16; s > 0; s >>= 1)
            acc += __shfl_xor_sync(0xffffffff, acc, s);
        if (lane == 0) {
            float v = acc + bias[oc];
            if (head) v = fminf(fmaxf(v, -20.f), 2.f);
            o[(size_t)b * NACT + oc] = v;
        }
    }
}

// ---------------------------------------------------------------------------
extern "C" void kernel_launch(void* const* d_in, const int* in_sizes, int n_in,
                              void* d_out, int out_size)
{
    const float* state = (const float*)d_in[0];
    const float* w1  = (const float*)d_in[1];  const float* b1  = (const float*)d_in[2];
    const float* w2  = (const float*)d_in[3];  const float* b2  = (const float*)d_in[4];
    const float* w3  = (const float*)d_in[5];  const float* b3  = (const float*)d_in[6];
    const float* wl  = (const float*)d_in[7];  const float* bl  = (const float*)d_in[8];
    const float* w11 = (const float*)d_in[9];  const float* b11 = (const float*)d_in[10];
    const float* w12 = (const float*)d_in[11]; const float* b12 = (const float*)d_in[12];
    const float* w21 = (const float*)d_in[13]; const float* b21 = (const float*)d_in[14];
    const float* w22 = (const float*)d_in[15]; const float* b22 = (const float*)d_in[16];
    const float* wm  = (const float*)d_in[17]; const float* bm  = (const float*)d_in[18];
    const float* ws  = (const float*)d_in[19]; const float* bs  = (const float*)d_in[20];
    float* out = (float*)d_out;

    float *pI, *pB123, *pBh1, *pH2m, *pH2s, *pIrep;
    __half *pAc, *pW123c, *pXc, *pWh1c, *pH1m, *pH1s, *pW12c, *pW22c;
    int *pFlag, *pCnt;
    cudaGetSymbolAddress((void**)&pI,     g_I);
    cudaGetSymbolAddress((void**)&pAc,    g_Ac);
    cudaGetSymbolAddress((void**)&pW123c, g_W123c);
    cudaGetSymbolAddress((void**)&pB123,  g_b123);
    cudaGetSymbolAddress((void**)&pXc,    g_Xc);
    cudaGetSymbolAddress((void**)&pWh1c,  g_Wh1c);
    cudaGetSymbolAddress((void**)&pBh1,   g_bh1);
    cudaGetSymbolAddress((void**)&pH1m,   g_H1m);
    cudaGetSymbolAddress((void**)&pH1s,   g_H1s);
    cudaGetSymbolAddress((void**)&pW12c,  g_W12c);
    cudaGetSymbolAddress((void**)&pW22c,  g_W22c);
    cudaGetSymbolAddress((void**)&pH2m,   g_H2m);
    cudaGetSymbolAddress((void**)&pH2s,   g_H2s);
    cudaGetSymbolAddress((void**)&pFlag,  g_flag);
    cudaGetSymbolAddress((void**)&pCnt,   g_cnt);
    cudaGetSymbolAddress((void**)&pIrep,  g_Irep);

    cudaFuncSetAttribute(gemm_mma<0>, cudaFuncAttributeMaxDynamicSharedMemorySize, SMEM_GEMM);
    cudaFuncSetAttribute(gemm_mma<1>, cudaFuncAttributeMaxDynamicSharedMemorySize, SMEM_GEMM);
    cudaFuncSetAttribute(gemm_mma<2>, cudaFuncAttributeMaxDynamicSharedMemorySize, SMEM_GEMM);

    const dim3 blk(256);

    cudaMemsetAsync(pCnt, 0, sizeof(int));

    // ---- operand prep ----
    {
        int n = BATCH * FRAMES * NIN;
        split_concat_A<<<(n + 255) / 256, blk>>>(state, pAc, NIN, n);
        n = HID * NIN;
        split_concat_B<<<(n + 255) / 256, blk>>>(w1, pW123c + (size_t)0 * HID * 3 * NIN, NIN, n);
        split_concat_B<<<(n + 255) / 256, blk>>>(w2, pW123c + (size_t)1 * HID * 3 * NIN, NIN, n);
        split_concat_B<<<(n + 255) / 256, blk>>>(w3, pW123c + (size_t)2 * HID * 3 * NIN, NIN, n);
        n = HID * 4 * HID;
        split2B_scaled<<<(n + 255) / 256, blk>>>(w11, pWh1c, 1.f / 15.f, 4 * HID, n);
        split2B_scaled<<<(n + 255) / 256, blk>>>(w21, pWh1c + (size_t)HID * 2 * 4 * HID,
                                                 1.f / 15.f, 4 * HID, n);
        n = HID * HID;
        split_concat_B<<<(n + 255) / 256, blk>>>(w12, pW12c, HID, n);
        split_concat_B<<<(n + 255) / 256, blk>>>(w22, pW22c, HID, n);

        cudaMemcpyAsync(pB123,           b1,  HID * 4, cudaMemcpyDeviceToDevice);
        cudaMemcpyAsync(pB123 + HID,     b2,  HID * 4, cudaMemcpyDeviceToDevice);
        cudaMemcpyAsync(pB123 + 2 * HID, b3,  HID * 4, cudaMemcpyDeviceToDevice);
        cudaMemcpyAsync(pBh1,            b11, HID * 4, cudaMemcpyDeviceToDevice);
        cudaMemcpyAsync(pBh1 + HID,      b21, HID * 4, cudaMemcpyDeviceToDevice);
    }

    // ---- phase 1: stacked fp16 3-product GEMM (K'=1536) -> g_I[b,f,j,h] ----
    {
        const dim3 g(3 * HID / 128, BATCH * FRAMES / 128);   // (24, 80)
        gemm_mma<0><<<g, blk, SMEM_GEMM>>>(BATCH * FRAMES, 3 * HID, 3 * NIN,
            pAc, pW123c, pB123, pI, 3 * HID, nullptr, nullptr);
    }

    // ---- phase 2: LIF scan + flag, then exact repair ----
    scan_flag_kernel<<<(BATCH * HID) / 256, blk>>>(pI, wl, bl, pXc, pFlag, pCnt);
    repair_dots_kernel<<<(MAXFLAG * 15 + 255) / 256, blk>>>(
        state, w1, b1, w2, b2, w3, b3, pFlag, pCnt, pIrep);
    repair_scan_kernel<<<(MAXFLAG + 255) / 256, blk>>>(pIrep, wl, bl, pFlag, pCnt, pXc);

    // ---- phase 3: heads on fp16 HMMA ----
    {   // layer 1, both heads stacked along N (K'=8192)
        const dim3 g(2 * HID / 128, BATCH / 128);
        gemm_mma<2><<<g, blk, SMEM_GEMM>>>(BATCH, 2 * HID, 2 * 4 * HID,
            pXc, pWh1c, pBh1, nullptr, 0, pH1m, pH1s);
    }
    {   // layer 2, both heads (K'=3072)
        const dim3 g(HID / 128, BATCH / 128);
        gemm_mma<1><<<g, blk, SMEM_GEMM>>>(BATCH, HID, 3 * HID,
            pH1m, pW12c, b12, pH2m, HID, nullptr, nullptr);
        gemm_mma<1><<<g, blk, SMEM_GEMM>>>(BATCH, HID, 3 * HID,
            pH1s, pW22c, b22, pH2s, HID, nullptr, nullptr);
    }
    // fused output layer, both heads in one launch
    head_out_kernel<<<dim3(BATCH, 2), blk>>>(pH2m, pH2s, wm, ws, bm, bs, out);
}